// round 3
// baseline (speedup 1.0000x reference)
#include <cuda_runtime.h>
#include <math.h>

#define N_NODES 30000
#define N_EDGES 480000

// ---------------- scratch (static device globals; no allocation) ----------------
__device__ float g_kqv[N_NODES * 768];     // k|q|v packed, reused by both layers
__device__ float g_kp [N_NODES * 256];     // relation-transformed K
__device__ float g_vp [N_NODES * 256];     // relation-transformed V
__device__ float g_alpha[N_EDGES * 4];     // logits, then exp() in-place
__device__ float g_amax [N_NODES * 4];
__device__ float g_denom[N_NODES * 4];
__device__ float g_agg[N_NODES * 256];
__device__ float g_tmp[N_NODES * 256];     // out1 pre-BN
__device__ float g_h  [N_NODES * 256];     // post BN+ReLU (needed for skip)
__device__ float g_bnsum[256];
__device__ float g_bnsq [256];

// ---------------- helpers ----------------
__device__ __forceinline__ float gelu_exact(float v) {
    return 0.5f * v * (1.0f + erff(v * 0.70710678118654752f));
}

__device__ __forceinline__ void atomicMaxFloat(float* addr, float value) {
    int* ai = (int*)addr;
    int old = *ai;
    while (value > __int_as_float(old)) {
        int assumed = old;
        old = atomicCAS(ai, assumed, __float_as_int(value));
        if (old == assumed) break;
    }
}

// ---------------- generic fill ----------------
__global__ void fill_kernel(float* __restrict__ p, float v, int n) {
    int i = blockIdx.x * blockDim.x + threadIdx.x;
    if (i < n) p[i] = v;
}

// ---------------- tiled fp32 GEMM: C[M,N] = act(A)[M,K] @ B[K,N] (+bias) ----------------
// ACT: 0 = identity on A, 1 = exact gelu on A elements
// BATCH_STRIDE mode: blockIdx.z = h selects A += h*64 (cols), B += h*4096, C += h*64 (cols)
template <int ACT, int BATCHED>
__global__ void gemm_kernel(const float* __restrict__ A, const float* __restrict__ B,
                            const float* __restrict__ bias, float* __restrict__ C,
                            int M, int K, int N, int lda, int ldb, int ldc) {
    if (BATCHED) {
        int h = blockIdx.z;
        A += h * 64;          // head slice of kqv columns
        B += h * 4096;        // [64,64] relation matrix for head h
        C += h * 64;          // head slice of output columns
    }
    __shared__ float As[16][65];   // [k][m]
    __shared__ float Bs[16][65];   // [k][n]
    const int bm = blockIdx.y * 64;
    const int bn = blockIdx.x * 64;
    const int tid = threadIdx.x;             // 256 threads
    const int tm = (tid / 16) * 4;
    const int tn = (tid % 16) * 4;

    float acc[4][4] = {};

    for (int k0 = 0; k0 < K; k0 += 16) {
        #pragma unroll
        for (int i = tid; i < 64 * 16; i += 256) {
            int m = i >> 4, kk = i & 15;
            int gm = bm + m, gk = k0 + kk;
            float v = 0.f;
            if (gm < M && gk < K) v = A[(size_t)gm * lda + gk];
            if (ACT) v = gelu_exact(v);
            As[kk][m] = v;
        }
        #pragma unroll
        for (int i = tid; i < 16 * 64; i += 256) {
            int kk = i >> 6, n = i & 63;
            int gk = k0 + kk, gn = bn + n;
            float v = 0.f;
            if (gk < K && gn < N) v = B[(size_t)gk * ldb + gn];
            Bs[kk][n] = v;
        }
        __syncthreads();
        #pragma unroll
        for (int kk = 0; kk < 16; kk++) {
            float a[4], b[4];
            #pragma unroll
            for (int i = 0; i < 4; i++) a[i] = As[kk][tm + i];
            #pragma unroll
            for (int j = 0; j < 4; j++) b[j] = Bs[kk][tn + j];
            #pragma unroll
            for (int i = 0; i < 4; i++)
                #pragma unroll
                for (int j = 0; j < 4; j++)
                    acc[i][j] += a[i] * b[j];
        }
        __syncthreads();
    }

    #pragma unroll
    for (int i = 0; i < 4; i++) {
        int gm = bm + tm + i;
        if (gm >= M) continue;
        #pragma unroll
        for (int j = 0; j < 4; j++) {
            int gn = bn + tn + j;
            if (gn >= N) continue;
            float v = acc[i][j];
            if (bias) v += bias[gn];
            C[(size_t)gm * ldc + gn] = v;
        }
    }
}

// ---------------- edge logits + segment max ----------------
// One warp per edge. HD = H*D = 256 always. Each lane owns 8 contiguous floats.
template <int H>
__global__ void alpha_kernel(const float* __restrict__ q, int ldq,
                             const float* __restrict__ kp,
                             const int* __restrict__ src, const int* __restrict__ dst,
                             const float* __restrict__ p_rel,
                             float* __restrict__ alpha, float* __restrict__ amax,
                             int E, float inv_sqrt_d) {
    int e = blockIdx.x * (blockDim.x >> 5) + (threadIdx.x >> 5);
    if (e >= E) return;
    int lane = threadIdx.x & 31;
    int s = src[e], d0 = dst[e];
    const float4* qv = (const float4*)(q + (size_t)d0 * ldq);
    const float4* kv = (const float4*)(kp + (size_t)s * 256);
    float4 q1 = qv[lane * 2], q2 = qv[lane * 2 + 1];
    float4 k1 = kv[lane * 2], k2 = kv[lane * 2 + 1];
    float part = q1.x * k1.x + q1.y * k1.y + q1.z * k1.z + q1.w * k1.w
               + q2.x * k2.x + q2.y * k2.y + q2.z * k2.z + q2.w * k2.w;
    const int G = 32 / H;   // lanes per head
    #pragma unroll
    for (int off = G / 2; off > 0; off >>= 1)
        part += __shfl_down_sync(0xffffffffu, part, off, G);
    if ((lane & (G - 1)) == 0) {
        int h = lane / G;
        float a = part * p_rel[h] * inv_sqrt_d;
        alpha[(size_t)e * H + h] = a;
        atomicMaxFloat(&amax[d0 * H + h], a);
    }
}

// ---------------- exp + segment sum (alpha -> ex in place) ----------------
__global__ void ex_kernel(float* __restrict__ alpha, const int* __restrict__ dst,
                          const float* __restrict__ amax, float* __restrict__ denom,
                          int EH, int H) {
    int i = blockIdx.x * blockDim.x + threadIdx.x;
    if (i >= EH) return;
    int e = i / H, h = i - e * H;
    int d0 = dst[e];
    float ex = expf(alpha[i] - amax[d0 * H + h]);
    alpha[i] = ex;
    atomicAdd(&denom[d0 * H + h], ex);
}

// ---------------- weighted scatter-add aggregation ----------------
__global__ void agg_kernel(const float* __restrict__ ex, const float* __restrict__ denom,
                           const float* __restrict__ vp, const int* __restrict__ src,
                           const int* __restrict__ dst, float* __restrict__ agg,
                           int E, int H) {
    int e = blockIdx.x * (blockDim.x >> 5) + (threadIdx.x >> 5);
    if (e >= E) return;
    int lane = threadIdx.x & 31;
    int s = src[e], d0 = dst[e];
    int G = 32 / H;
    int h = lane / G;
    float c = ex[(size_t)e * H + h] / (denom[d0 * H + h] + 1e-16f);
    const float4* vv = (const float4*)(vp + (size_t)s * 256);
    float4 v1 = vv[lane * 2], v2 = vv[lane * 2 + 1];
    float* o = agg + (size_t)d0 * 256 + lane * 8;
    atomicAdd(o + 0, c * v1.x); atomicAdd(o + 1, c * v1.y);
    atomicAdd(o + 2, c * v1.z); atomicAdd(o + 3, c * v1.w);
    atomicAdd(o + 4, c * v2.x); atomicAdd(o + 5, c * v2.y);
    atomicAdd(o + 6, c * v2.z); atomicAdd(o + 7, c * v2.w);
}

// ---------------- BN stats ----------------
__global__ void bn_stats_kernel(const float* __restrict__ x, float* __restrict__ sum,
                                float* __restrict__ sumsq, int n) {
    int col = threadIdx.x;   // 256 threads, one column each
    float s = 0.f, s2 = 0.f;
    for (int r = blockIdx.x; r < n; r += gridDim.x) {
        float v = x[(size_t)r * 256 + col];
        s += v; s2 += v * v;
    }
    atomicAdd(&sum[col], s);
    atomicAdd(&sumsq[col], s2);
}

// ---------------- BN apply + ReLU ----------------
__global__ void bn_apply_kernel(const float* __restrict__ x, float* __restrict__ y,
                                const float* __restrict__ sum, const float* __restrict__ sumsq,
                                const float* __restrict__ gamma, const float* __restrict__ beta,
                                int n) {
    int i = blockIdx.x * blockDim.x + threadIdx.x;
    if (i >= n * 256) return;
    int col = i & 255;
    float inv_n = 1.0f / (float)n;
    float mu = sum[col] * inv_n;
    float var = sumsq[col] * inv_n - mu * mu;
    float v = (x[i] - mu) * rsqrtf(var + 1e-5f) * gamma[col] + beta[col];
    y[i] = fmaxf(v, 0.f);
}

// ---------------- final skip gate ----------------
__global__ void skip_kernel(float* __restrict__ out, const float* __restrict__ h,
                            const float* __restrict__ skip, int n) {
    int i = blockIdx.x * blockDim.x + threadIdx.x;
    if (i >= n) return;
    float s = 1.0f / (1.0f + expf(-skip[0]));
    out[i] = s * out[i] + (1.0f - s) * h[i];
}

// ---------------- host orchestration ----------------
extern "C" void kernel_launch(void* const* d_in, const int* in_sizes, int n_in,
                              void* d_out, int out_size) {
    const float* x       = (const float*)d_in[0];
    const int*   ei      = (const int*)  d_in[1];
    const float* w_kqv1  = (const float*)d_in[2];
    const float* b_kqv1  = (const float*)d_in[3];
    const float* k_rel1  = (const float*)d_in[4];
    const float* v_rel1  = (const float*)d_in[5];
    const float* p_rel1  = (const float*)d_in[6];
    const float* w_out1  = (const float*)d_in[7];
    const float* b_out1  = (const float*)d_in[8];
    // skip1 (d_in[9]) unused: layer-1 in/out dims differ -> no skip gate
    const float* bn_gamma = (const float*)d_in[10];
    const float* bn_beta  = (const float*)d_in[11];
    const float* w_kqv2  = (const float*)d_in[12];
    const float* b_kqv2  = (const float*)d_in[13];
    const float* k_rel2  = (const float*)d_in[14];
    const float* v_rel2  = (const float*)d_in[15];
    const float* p_rel2  = (const float*)d_in[16];
    const float* w_out2  = (const float*)d_in[17];
    const float* b_out2  = (const float*)d_in[18];
    const float* skip2   = (const float*)d_in[19];

    const int* src = ei;
    const int* dst = ei + N_EDGES;
    float* outp = (float*)d_out;

    float *kqv, *kp, *vp, *alpha, *amax, *denom, *agg, *tmp, *hbuf, *bnsum, *bnsq;
    cudaGetSymbolAddress((void**)&kqv,   g_kqv);
    cudaGetSymbolAddress((void**)&kp,    g_kp);
    cudaGetSymbolAddress((void**)&vp,    g_vp);
    cudaGetSymbolAddress((void**)&alpha, g_alpha);
    cudaGetSymbolAddress((void**)&amax,  g_amax);
    cudaGetSymbolAddress((void**)&denom, g_denom);
    cudaGetSymbolAddress((void**)&agg,   g_agg);
    cudaGetSymbolAddress((void**)&tmp,   g_tmp);
    cudaGetSymbolAddress((void**)&hbuf,  g_h);
    cudaGetSymbolAddress((void**)&bnsum, g_bnsum);
    cudaGetSymbolAddress((void**)&bnsq,  g_bnsq);

    const float ninf = -INFINITY;
    const int NH = N_NODES * 256;
    const int MT = (N_NODES + 63) / 64;   // 469 row tiles

    auto fill = [&](float* p, float v, int n) {
        fill_kernel<<<(n + 255) / 256, 256>>>(p, v, n);
    };

    // ================= Layer 1 (heads=4, d=64) =================
    fill(amax, ninf, N_NODES * 4);
    fill(denom, 0.f, N_NODES * 4);
    fill(agg, 0.f, NH);
    fill(bnsum, 0.f, 256);
    fill(bnsq, 0.f, 256);

    // kqv1 = x @ w_kqv1 + b  : [30000,512]x[512,768]
    gemm_kernel<0,0><<<dim3(768 / 64, MT), 256>>>(x, w_kqv1, b_kqv1, kqv,
                                                  N_NODES, 512, 768, 512, 768, 768);
    // per-head relation transforms, batched over blockIdx.z = head
    gemm_kernel<0,1><<<dim3(1, MT, 4), 256>>>(kqv,       k_rel1, nullptr, kp,
                                              N_NODES, 64, 64, 768, 64, 256);
    gemm_kernel<0,1><<<dim3(1, MT, 4), 256>>>(kqv + 512, v_rel1, nullptr, vp,
                                              N_NODES, 64, 64, 768, 64, 256);
    // edge logits + segment max (q lives at kqv cols [256,512))
    alpha_kernel<4><<<(N_EDGES + 7) / 8, 256>>>(kqv + 256, 768, kp, src, dst, p_rel1,
                                                alpha, amax, N_EDGES, 0.125f);
    ex_kernel<<<(N_EDGES * 4 + 255) / 256, 256>>>(alpha, dst, amax, denom, N_EDGES * 4, 4);
    agg_kernel<<<(N_EDGES + 7) / 8, 256>>>(alpha, denom, vp, src, dst, agg, N_EDGES, 4);
    // out1 = gelu(agg) @ w_out1 + b_out1
    gemm_kernel<1,0><<<dim3(256 / 64, MT), 256>>>(agg, w_out1, b_out1, tmp,
                                                  N_NODES, 256, 256, 256, 256, 256);
    // BN (batch stats) + ReLU -> hbuf
    bn_stats_kernel<<<256, 256>>>(tmp, bnsum, bnsq, N_NODES);
    bn_apply_kernel<<<(NH + 255) / 256, 256>>>(tmp, hbuf, bnsum, bnsq, bn_gamma, bn_beta, N_NODES);

    // ================= Layer 2 (heads=1, d=256) =================
    fill(amax, ninf, N_NODES);
    fill(denom, 0.f, N_NODES);
    fill(agg, 0.f, NH);

    gemm_kernel<0,0><<<dim3(768 / 64, MT), 256>>>(hbuf, w_kqv2, b_kqv2, kqv,
                                                  N_NODES, 256, 768, 256, 768, 768);
    gemm_kernel<0,0><<<dim3(256 / 64, MT), 256>>>(kqv,       k_rel2, nullptr, kp,
                                                  N_NODES, 256, 256, 768, 256, 256);
    gemm_kernel<0,0><<<dim3(256 / 64, MT), 256>>>(kqv + 512, v_rel2, nullptr, vp,
                                                  N_NODES, 256, 256, 768, 256, 256);
    alpha_kernel<1><<<(N_EDGES + 7) / 8, 256>>>(kqv + 256, 768, kp, src, dst, p_rel2,
                                                alpha, amax, N_EDGES, 0.0625f);
    ex_kernel<<<(N_EDGES + 255) / 256, 256>>>(alpha, dst, amax, denom, N_EDGES, 1);
    agg_kernel<<<(N_EDGES + 7) / 8, 256>>>(alpha, denom, vp, src, dst, agg, N_EDGES, 1);
    // out2 = gelu(agg) @ w_out2 + b_out2 -> d_out
    gemm_kernel<1,0><<<dim3(256 / 64, MT), 256>>>(agg, w_out2, b_out2, outp,
                                                  N_NODES, 256, 256, 256, 256, 256);
    // skip gate with hbuf
    skip_kernel<<<(NH + 255) / 256, 256>>>(outp, hbuf, skip2, NH);

    (void)in_sizes; (void)n_in; (void)out_size;
}

// round 4
// speedup vs baseline: 2.2340x; 2.2340x over previous
#include <cuda_runtime.h>
#include <math.h>

#define N_NODES 30000
#define N_EDGES 480000

// ---------------- scratch (static device globals; no allocation) ----------------
__device__ float g_kqv[N_NODES * 768];     // k|q|v packed, reused by both layers
__device__ float g_kp [N_NODES * 256];     // relation-transformed K
__device__ float g_vp [N_NODES * 256];     // relation-transformed V
__device__ float g_alpha[N_EDGES * 4];     // logits
__device__ unsigned int g_amax[N_NODES * 4];   // encoded-float max
__device__ float g_denom[N_NODES * 4];
__device__ float g_agg[N_NODES * 256];     // unnormalized weighted sum
__device__ float g_tmp[N_NODES * 256];     // out1 pre-BN
__device__ float g_h  [N_NODES * 256];     // post BN+ReLU (needed for skip)
__device__ float g_bnsum[256];
__device__ float g_bnsq [256];

// ---------------- helpers ----------------
__device__ __forceinline__ float gelu_exact(float v) {
    return 0.5f * v * (1.0f + erff(v * 0.70710678118654752f));
}

// monotone float -> uint encoding (order-preserving), enables atomicMax on uint
__device__ __forceinline__ unsigned int enc_f(float f) {
    unsigned int u = __float_as_uint(f);
    return (u & 0x80000000u) ? ~u : (u | 0x80000000u);
}
__device__ __forceinline__ float dec_f(unsigned int e) {
    unsigned int u = (e & 0x80000000u) ? (e & 0x7fffffffu) : ~e;
    return __uint_as_float(u);
}

__device__ __forceinline__ void red_add_v4(float* addr, float a, float b, float c, float d) {
    asm volatile("red.global.add.v4.f32 [%0], {%1, %2, %3, %4};"
                 :: "l"(addr), "f"(a), "f"(b), "f"(c), "f"(d) : "memory");
}

// ---------------- fills ----------------
__global__ void fillf_kernel(float* __restrict__ p, float v, int n) {
    int i = blockIdx.x * blockDim.x + threadIdx.x;
    if (i < n) p[i] = v;
}
__global__ void fillu_kernel(unsigned int* __restrict__ p, unsigned int v, int n) {
    int i = blockIdx.x * blockDim.x + threadIdx.x;
    if (i < n) p[i] = v;
}

// ---------------- big tiled fp32 GEMM: 128x128x16, 8x8 microtile ----------------
// C[M,N] = act(A)[M,K] @ B[K,N] (+bias) (+skip-gate blend with hres)
// ACT: 0 = identity, 2 = gelu(a / (denom[row,head]+1e-16))
// Requirements: K % 16 == 0, N % 128 == 0, A/B/C float4-aligned rows.
template <int ACT, int SKIP>
__global__ void gemm128(const float* __restrict__ A, const float* __restrict__ B,
                        const float* __restrict__ bias, float* __restrict__ C,
                        int M, int K, int N, int lda, int ldb, int ldc,
                        const float* __restrict__ denom, int dshift, int H,
                        const float* __restrict__ skipv, const float* __restrict__ hres) {
    __shared__ float As[16][132];
    __shared__ float Bs[16][128];
    const int bm = blockIdx.y * 128;
    const int bn = blockIdx.x * 128;
    const int tid = threadIdx.x;          // 256 threads
    const int tm = (tid >> 4) * 8;        // 0..120
    const int tn = (tid & 15) * 8;        // 0..120

    float acc[8][8] = {};

    for (int k0 = 0; k0 < K; k0 += 16) {
        // ---- load A tile (128 x 16) as 512 float4, store transposed ----
        #pragma unroll
        for (int l = 0; l < 2; l++) {
            int i = tid + l * 256;
            int row = i >> 2;            // 0..127
            int kq  = (i & 3) * 4;       // 0,4,8,12
            int gm = bm + row;
            float4 v = make_float4(0.f, 0.f, 0.f, 0.f);
            if (gm < M) v = *(const float4*)(A + (size_t)gm * lda + k0 + kq);
            if (ACT == 2) {
                int h = (k0 + kq) >> dshift;
                int gi = (gm < M) ? gm : 0;
                float invd = 1.0f / (denom[gi * H + h] + 1e-16f);
                v.x = gelu_exact(v.x * invd);
                v.y = gelu_exact(v.y * invd);
                v.z = gelu_exact(v.z * invd);
                v.w = gelu_exact(v.w * invd);
            }
            As[kq + 0][row] = v.x;
            As[kq + 1][row] = v.y;
            As[kq + 2][row] = v.z;
            As[kq + 3][row] = v.w;
        }
        // ---- load B tile (16 x 128) as 512 float4 ----
        #pragma unroll
        for (int l = 0; l < 2; l++) {
            int i = tid + l * 256;
            int row = i >> 5;            // 0..15
            int c4  = (i & 31) * 4;      // 0..124
            *(float4*)&Bs[row][c4] = *(const float4*)(B + (size_t)(k0 + row) * ldb + bn + c4);
        }
        __syncthreads();
        // ---- 8x8 microtile FMA ----
        #pragma unroll
        for (int kk = 0; kk < 16; kk++) {
            float a[8], b[8];
            *(float4*)(a)     = *(float4*)&As[kk][tm];
            *(float4*)(a + 4) = *(float4*)&As[kk][tm + 4];
            *(float4*)(b)     = *(float4*)&Bs[kk][tn];
            *(float4*)(b + 4) = *(float4*)&Bs[kk][tn + 4];
            #pragma unroll
            for (int i = 0; i < 8; i++)
                #pragma unroll
                for (int j = 0; j < 8; j++)
                    acc[i][j] += a[i] * b[j];
        }
        __syncthreads();
    }

    float s = 1.f, s1 = 0.f;
    if (SKIP) {
        s = 1.0f / (1.0f + expf(-skipv[0]));
        s1 = 1.0f - s;
    }
    #pragma unroll
    for (int i = 0; i < 8; i++) {
        int gm = bm + tm + i;
        if (gm >= M) continue;
        #pragma unroll
        for (int jj = 0; jj < 2; jj++) {
            int gn = bn + tn + jj * 4;
            float4 o;
            o.x = acc[i][jj * 4 + 0];
            o.y = acc[i][jj * 4 + 1];
            o.z = acc[i][jj * 4 + 2];
            o.w = acc[i][jj * 4 + 3];
            if (bias) {
                o.x += bias[gn + 0]; o.y += bias[gn + 1];
                o.z += bias[gn + 2]; o.w += bias[gn + 3];
            }
            if (SKIP) {
                const float* hb = hres + (size_t)gm * ldc + gn;
                o.x = s * o.x + s1 * hb[0];
                o.y = s * o.y + s1 * hb[1];
                o.z = s * o.z + s1 * hb[2];
                o.w = s * o.w + s1 * hb[3];
            }
            *(float4*)(C + (size_t)gm * ldc + gn) = o;
        }
    }
}

// ---------------- small batched GEMM for layer-1 relation transforms ----------------
// blockIdx.z = head h: A += h*64 (cols of kqv), B += h*4096, C += h*64 (cols)
__global__ void gemm_rel1(const float* __restrict__ A, const float* __restrict__ B,
                          float* __restrict__ C, int M, int lda, int ldc) {
    int h = blockIdx.z;
    A += h * 64;
    B += h * 4096;
    C += h * 64;
    __shared__ float As[16][65];
    __shared__ float Bs[16][65];
    const int bm = blockIdx.y * 64;
    const int tid = threadIdx.x;  // 256
    const int tm = (tid / 16) * 4;
    const int tn = (tid % 16) * 4;
    float acc[4][4] = {};
    for (int k0 = 0; k0 < 64; k0 += 16) {
        #pragma unroll
        for (int i = tid; i < 64 * 16; i += 256) {
            int m = i >> 4, kk = i & 15;
            int gm = bm + m;
            As[kk][m] = (gm < M) ? A[(size_t)gm * lda + k0 + kk] : 0.f;
        }
        #pragma unroll
        for (int i = tid; i < 16 * 64; i += 256) {
            int kk = i >> 6, n = i & 63;
            Bs[kk][n] = B[(size_t)(k0 + kk) * 64 + n];
        }
        __syncthreads();
        #pragma unroll
        for (int kk = 0; kk < 16; kk++) {
            float a[4], b[4];
            #pragma unroll
            for (int i = 0; i < 4; i++) a[i] = As[kk][tm + i];
            #pragma unroll
            for (int j = 0; j < 4; j++) b[j] = Bs[kk][tn + j];
            #pragma unroll
            for (int i = 0; i < 4; i++)
                #pragma unroll
                for (int j = 0; j < 4; j++)
                    acc[i][j] += a[i] * b[j];
        }
        __syncthreads();
    }
    #pragma unroll
    for (int i = 0; i < 4; i++) {
        int gm = bm + tm + i;
        if (gm >= M) continue;
        #pragma unroll
        for (int j = 0; j < 4; j++)
            C[(size_t)gm * ldc + tn + j] = acc[i][j];
    }
}

// ---------------- edge logits + segment max (encoded atomicMax) ----------------
// One warp per edge; 256 floats of q & kp per edge, 8 per lane.
template <int H>
__global__ void alpha_kernel(const float* __restrict__ q, int ldq,
                             const float* __restrict__ kp,
                             const int* __restrict__ src, const int* __restrict__ dst,
                             const float* __restrict__ p_rel,
                             float* __restrict__ alpha, unsigned int* __restrict__ amax,
                             int E, float inv_sqrt_d) {
    int e = blockIdx.x * (blockDim.x >> 5) + (threadIdx.x >> 5);
    if (e >= E) return;
    int lane = threadIdx.x & 31;
    int s = src[e], d0 = dst[e];
    const float4* qv = (const float4*)(q + (size_t)d0 * ldq);
    const float4* kv = (const float4*)(kp + (size_t)s * 256);
    float4 q1 = qv[lane * 2], q2 = qv[lane * 2 + 1];
    float4 k1 = kv[lane * 2], k2 = kv[lane * 2 + 1];
    float part = q1.x * k1.x + q1.y * k1.y + q1.z * k1.z + q1.w * k1.w
               + q2.x * k2.x + q2.y * k2.y + q2.z * k2.z + q2.w * k2.w;
    const int G = 32 / H;   // lanes per head
    #pragma unroll
    for (int off = G / 2; off > 0; off >>= 1)
        part += __shfl_down_sync(0xffffffffu, part, off, G);
    if ((lane & (G - 1)) == 0) {
        int h = lane / G;
        float a = part * p_rel[h] * inv_sqrt_d;
        alpha[(size_t)e * H + h] = a;
        atomicMax(&amax[d0 * H + h], enc_f(a));
    }
}

// ---------------- fused exp + denom + weighted scatter-add ----------------
// agg accumulates sum(ex * vp); normalization by denom deferred to the out-GEMM.
template <int H>
__global__ void agg_fused_kernel(const float* __restrict__ alpha,
                                 const unsigned int* __restrict__ amax,
                                 float* __restrict__ denom,
                                 const float* __restrict__ vp,
                                 const int* __restrict__ src, const int* __restrict__ dst,
                                 float* __restrict__ agg, int E) {
    int e = blockIdx.x * (blockDim.x >> 5) + (threadIdx.x >> 5);
    if (e >= E) return;
    int lane = threadIdx.x & 31;
    int s = src[e], d0 = dst[e];
    const int G = 32 / H;
    int h = lane / G;
    float am = dec_f(amax[d0 * H + h]);
    float ex = expf(alpha[(size_t)e * H + h] - am);
    if ((lane & (G - 1)) == 0)
        atomicAdd(&denom[d0 * H + h], ex);
    const float4* vv = (const float4*)(vp + (size_t)s * 256);
    float4 v1 = vv[lane * 2], v2 = vv[lane * 2 + 1];
    float* o = agg + (size_t)d0 * 256 + lane * 8;
    red_add_v4(o,     ex * v1.x, ex * v1.y, ex * v1.z, ex * v1.w);
    red_add_v4(o + 4, ex * v2.x, ex * v2.y, ex * v2.z, ex * v2.w);
}

// ---------------- BN stats ----------------
__global__ void bn_stats_kernel(const float* __restrict__ x, float* __restrict__ sum,
                                float* __restrict__ sumsq, int n) {
    int col = threadIdx.x;   // 256 threads, one column each
    float s = 0.f, s2 = 0.f;
    for (int r = blockIdx.x; r < n; r += gridDim.x) {
        float v = x[(size_t)r * 256 + col];
        s += v; s2 += v * v;
    }
    atomicAdd(&sum[col], s);
    atomicAdd(&sumsq[col], s2);
}

// ---------------- BN apply + ReLU ----------------
__global__ void bn_apply_kernel(const float* __restrict__ x, float* __restrict__ y,
                                const float* __restrict__ sum, const float* __restrict__ sumsq,
                                const float* __restrict__ gamma, const float* __restrict__ beta,
                                int n) {
    int i = blockIdx.x * blockDim.x + threadIdx.x;
    if (i >= n * 256) return;
    int col = i & 255;
    float inv_n = 1.0f / (float)n;
    float mu = sum[col] * inv_n;
    float var = sumsq[col] * inv_n - mu * mu;
    float v = (x[i] - mu) * rsqrtf(var + 1e-5f) * gamma[col] + beta[col];
    y[i] = fmaxf(v, 0.f);
}

// ---------------- host orchestration ----------------
extern "C" void kernel_launch(void* const* d_in, const int* in_sizes, int n_in,
                              void* d_out, int out_size) {
    const float* x       = (const float*)d_in[0];
    const int*   ei      = (const int*)  d_in[1];
    const float* w_kqv1  = (const float*)d_in[2];
    const float* b_kqv1  = (const float*)d_in[3];
    const float* k_rel1  = (const float*)d_in[4];
    const float* v_rel1  = (const float*)d_in[5];
    const float* p_rel1  = (const float*)d_in[6];
    const float* w_out1  = (const float*)d_in[7];
    const float* b_out1  = (const float*)d_in[8];
    // skip1 (d_in[9]) unused: layer-1 in/out dims differ -> no skip gate
    const float* bn_gamma = (const float*)d_in[10];
    const float* bn_beta  = (const float*)d_in[11];
    const float* w_kqv2  = (const float*)d_in[12];
    const float* b_kqv2  = (const float*)d_in[13];
    const float* k_rel2  = (const float*)d_in[14];
    const float* v_rel2  = (const float*)d_in[15];
    const float* p_rel2  = (const float*)d_in[16];
    const float* w_out2  = (const float*)d_in[17];
    const float* b_out2  = (const float*)d_in[18];
    const float* skip2   = (const float*)d_in[19];

    const int* src = ei;
    const int* dst = ei + N_EDGES;
    float* outp = (float*)d_out;

    float *kqv, *kp, *vp, *alpha, *denom, *agg, *tmp, *hbuf, *bnsum, *bnsq;
    unsigned int* amax;
    cudaGetSymbolAddress((void**)&kqv,   g_kqv);
    cudaGetSymbolAddress((void**)&kp,    g_kp);
    cudaGetSymbolAddress((void**)&vp,    g_vp);
    cudaGetSymbolAddress((void**)&alpha, g_alpha);
    cudaGetSymbolAddress((void**)&amax,  g_amax);
    cudaGetSymbolAddress((void**)&denom, g_denom);
    cudaGetSymbolAddress((void**)&agg,   g_agg);
    cudaGetSymbolAddress((void**)&tmp,   g_tmp);
    cudaGetSymbolAddress((void**)&hbuf,  g_h);
    cudaGetSymbolAddress((void**)&bnsum, g_bnsum);
    cudaGetSymbolAddress((void**)&bnsq,  g_bnsq);

    const unsigned int ENC_NINF = 0x007FFFFFu;  // enc(-inf)
    const int NH = N_NODES * 256;
    const int MT64  = (N_NODES + 63) / 64;
    const int MT128 = (N_NODES + 127) / 128;   // 235

    auto zero = [&](float* p, int n) {
        fillf_kernel<<<(n + 255) / 256, 256>>>(p, 0.f, n);
    };

    // ================= Layer 1 (heads=4, d=64) =================
    fillu_kernel<<<(N_NODES * 4 + 255) / 256, 256>>>(amax, ENC_NINF, N_NODES * 4);
    zero(denom, N_NODES * 4);
    zero(agg, NH);
    zero(bnsum, 256);
    zero(bnsq, 256);

    // kqv1 = x @ w_kqv1 + b : [30000,512] x [512,768]
    gemm128<0,0><<<dim3(768 / 128, MT128), 256>>>(x, w_kqv1, b_kqv1, kqv,
        N_NODES, 512, 768, 512, 768, 768, nullptr, 0, 0, nullptr, nullptr);
    // per-head relation transforms (batched over blockIdx.z)
    gemm_rel1<<<dim3(1, MT64, 4), 256>>>(kqv,       k_rel1, kp, N_NODES, 768, 256);
    gemm_rel1<<<dim3(1, MT64, 4), 256>>>(kqv + 512, v_rel1, vp, N_NODES, 768, 256);
    // edge logits + segment max (q at kqv cols [256,512))
    alpha_kernel<4><<<(N_EDGES + 7) / 8, 256>>>(kqv + 256, 768, kp, src, dst, p_rel1,
                                                alpha, amax, N_EDGES, 0.125f);
    // fused exp + denom + scatter-add
    agg_fused_kernel<4><<<(N_EDGES + 7) / 8, 256>>>(alpha, amax, denom, vp, src, dst,
                                                    agg, N_EDGES);
    // out1 = gelu(agg / denom) @ w_out1 + b_out1   (dshift=6 -> head = col/64, H=4)
    gemm128<2,0><<<dim3(256 / 128, MT128), 256>>>(agg, w_out1, b_out1, tmp,
        N_NODES, 256, 256, 256, 256, 256, denom, 6, 4, nullptr, nullptr);
    // BN (batch stats) + ReLU -> hbuf
    bn_stats_kernel<<<256, 256>>>(tmp, bnsum, bnsq, N_NODES);
    bn_apply_kernel<<<(NH + 255) / 256, 256>>>(tmp, hbuf, bnsum, bnsq, bn_gamma, bn_beta, N_NODES);

    // ================= Layer 2 (heads=1, d=256) =================
    fillu_kernel<<<(N_NODES + 255) / 256, 256>>>(amax, ENC_NINF, N_NODES);
    zero(denom, N_NODES);
    zero(agg, NH);

    gemm128<0,0><<<dim3(768 / 128, MT128), 256>>>(hbuf, w_kqv2, b_kqv2, kqv,
        N_NODES, 256, 768, 256, 768, 768, nullptr, 0, 0, nullptr, nullptr);
    gemm128<0,0><<<dim3(256 / 128, MT128), 256>>>(kqv, k_rel2, nullptr, kp,
        N_NODES, 256, 256, 768, 256, 256, nullptr, 0, 0, nullptr, nullptr);
    gemm128<0,0><<<dim3(256 / 128, MT128), 256>>>(kqv + 512, v_rel2, nullptr, vp,
        N_NODES, 256, 256, 768, 256, 256, nullptr, 0, 0, nullptr, nullptr);
    alpha_kernel<1><<<(N_EDGES + 7) / 8, 256>>>(kqv + 256, 768, kp, src, dst, p_rel2,
                                                alpha, amax, N_EDGES, 0.0625f);
    agg_fused_kernel<1><<<(N_EDGES + 7) / 8, 256>>>(alpha, amax, denom, vp, src, dst,
                                                    agg, N_EDGES);
    // out2 = gelu(agg / denom) @ w_out2 + b_out2, fused skip gate -> d_out
    gemm128<2,1><<<dim3(256 / 128, MT128), 256>>>(agg, w_out2, b_out2, outp,
        N_NODES, 256, 256, 256, 256, 256, denom, 8, 1, skip2, hbuf);

    (void)in_sizes; (void)n_in; (void)out_size;
}

// round 5
// speedup vs baseline: 3.8218x; 1.7108x over previous
#include <cuda_runtime.h>
#include <math.h>

#define N_NODES 30000
#define N_EDGES 480000

// ---------------- scratch (static device globals; no allocation) ----------------
__device__ float g_kqv[N_NODES * 768];     // kp|q|vp packed (both layers)
__device__ float g_alpha[N_EDGES * 4];     // logits
__device__ unsigned int g_amax[N_NODES * 4];   // encoded-float max
__device__ float g_denom[N_NODES * 4];
__device__ float g_agg[N_NODES * 256];     // unnormalized weighted sum
__device__ float g_tmp[N_NODES * 256];     // out1 pre-BN
__device__ float g_h  [N_NODES * 256];     // post BN+ReLU (needed for skip)
__device__ float g_bnsum[256];
__device__ float g_bnsq [256];
__device__ float g_w1p[512 * 768];         // combined L1 weights
__device__ float g_b1p[768];
__device__ float g_w2p[256 * 768];         // combined L2 weights
__device__ float g_b2p[768];

// ---------------- helpers ----------------
__device__ __forceinline__ float gelu_exact(float v) {
    return 0.5f * v * (1.0f + erff(v * 0.70710678118654752f));
}
__device__ __forceinline__ unsigned int enc_f(float f) {
    unsigned int u = __float_as_uint(f);
    return (u & 0x80000000u) ? ~u : (u | 0x80000000u);
}
__device__ __forceinline__ float dec_f(unsigned int e) {
    unsigned int u = (e & 0x80000000u) ? (e & 0x7fffffffu) : ~e;
    return __uint_as_float(u);
}
__device__ __forceinline__ void red_add_v4(float* addr, float a, float b, float c, float d) {
    asm volatile("red.global.add.v4.f32 [%0], {%1, %2, %3, %4};"
                 :: "l"(addr), "f"(a), "f"(b), "f"(c), "f"(d) : "memory");
}
__device__ __forceinline__ unsigned cvt_tf32(float f) {
    unsigned u;
    asm("cvt.rna.tf32.f32 %0, %1;" : "=r"(u) : "f"(f));
    return u;
}
__device__ __forceinline__ void mma_tf32(float* d, const unsigned* a, const unsigned* b) {
    asm volatile("mma.sync.aligned.m16n8k8.row.col.f32.tf32.tf32.f32 "
                 "{%0,%1,%2,%3}, {%4,%5,%6,%7}, {%8,%9}, {%0,%1,%2,%3};"
                 : "+f"(d[0]), "+f"(d[1]), "+f"(d[2]), "+f"(d[3])
                 : "r"(a[0]), "r"(a[1]), "r"(a[2]), "r"(a[3]), "r"(b[0]), "r"(b[1]));
}

// ---------------- fills ----------------
__global__ void fillf_kernel(float* __restrict__ p, float v, int n) {
    int i = blockIdx.x * blockDim.x + threadIdx.x;
    if (i < n) p[i] = v;
}
__global__ void fillu_kernel(unsigned int* __restrict__ p, unsigned int v, int n) {
    int i = blockIdx.x * blockDim.x + threadIdx.x;
    if (i < n) p[i] = v;
}

// ---------------- weight combine: W' = [Wk@Krel_bd | Wq | Wv@Vrel_bd], b' likewise ----------------
// cols [0,256): k path through k_rel; [256,512): copy q; [512,768): v path through v_rel.
// row == IN means transform the bias vector instead.
__global__ void combine_kernel(const float* __restrict__ W, const float* __restrict__ b,
                               const float* __restrict__ krel, const float* __restrict__ vrel,
                               float* __restrict__ Wp, float* __restrict__ bp,
                               int IN, int D) {
    int idx = blockIdx.x * blockDim.x + threadIdx.x;
    if (idx >= (IN + 1) * 768) return;
    int row = idx / 768, c = idx % 768;
    const float* src = (row < IN) ? (W + (size_t)row * 768) : b;
    float val;
    if (c >= 256 && c < 512) {
        val = src[c];
    } else {
        const float* rel = (c < 256) ? krel : vrel;
        int cc = (c < 256) ? c : (c - 512);
        int base = (c < 256) ? 0 : 512;
        int h = cc / D, e = cc % D;
        float s = 0.f;
        for (int d = 0; d < D; d++)
            s += src[base + h * D + d] * rel[(h * D + d) * D + e];
        val = s;
    }
    if (row < IN) Wp[(size_t)row * 768 + c] = val;
    else          bp[c] = val;
}

// ---------------- tf32 tensor-core GEMM: 128x128x16 tile, 8 warps of 32x64 ----------------
// C[M,N] = act(A)[M,K] @ B[K,N] (+bias) (+skip blend)
// ACT: 0 = identity, 2 = gelu(a / (denom[row,head]+1e-16)), head = k >> dshift
// Requirements: K % 16 == 0, N % 128 == 0, rows float4-aligned.
template <int ACT, int SKIP>
__global__ void gemm_tf32(const float* __restrict__ A, const float* __restrict__ B,
                          const float* __restrict__ bias, float* __restrict__ C,
                          int M, int K, int N, int lda, int ldb, int ldc,
                          const float* __restrict__ denom, int dshift, int H,
                          const float* __restrict__ skipv, const float* __restrict__ hres) {
    __shared__ unsigned As[128][20];    // m-major (pad 20 -> conflict-free frag loads)
    __shared__ unsigned Bs[16][136];    // k-major (pad 136 -> conflict-free frag loads)
    const int bm = blockIdx.y * 128;
    const int bn = blockIdx.x * 128;
    const int tid = threadIdx.x;        // 256
    const int wid = tid >> 5, lane = tid & 31;
    const int wm = (wid >> 1) * 32;     // warp m offset: 0,32,64,96
    const int wn = (wid & 1) * 64;      // warp n offset: 0,64
    const int gq = lane >> 2;           // 0..7
    const int qc = lane & 3;            // 0..3

    float acc[2][8][4] = {};

    for (int k0 = 0; k0 < K; k0 += 16) {
        // ---- A tile 128x16 (512 float4 loads), cvt->tf32, m-major store ----
        #pragma unroll
        for (int l = 0; l < 2; l++) {
            int i = tid + l * 256;
            int row = i >> 2, kq = (i & 3) * 4;
            int gm = bm + row;
            float4 v = make_float4(0.f, 0.f, 0.f, 0.f);
            if (gm < M) v = *(const float4*)(A + (size_t)gm * lda + k0 + kq);
            if (ACT == 2) {
                int gi = (gm < M) ? gm : 0;
                int h = (k0 + kq) >> dshift;          // 4-elem vec never crosses head
                float invd = 1.0f / (denom[gi * H + h] + 1e-16f);
                v.x = gelu_exact(v.x * invd);
                v.y = gelu_exact(v.y * invd);
                v.z = gelu_exact(v.z * invd);
                v.w = gelu_exact(v.w * invd);
            }
            uint4 u = make_uint4(cvt_tf32(v.x), cvt_tf32(v.y), cvt_tf32(v.z), cvt_tf32(v.w));
            *(uint4*)&As[row][kq] = u;
        }
        // ---- B tile 16x128 (512 float4 loads), cvt->tf32 ----
        #pragma unroll
        for (int l = 0; l < 2; l++) {
            int i = tid + l * 256;
            int row = i >> 5, c4 = (i & 31) * 4;
            float4 v = *(const float4*)(B + (size_t)(k0 + row) * ldb + bn + c4);
            uint4 u = make_uint4(cvt_tf32(v.x), cvt_tf32(v.y), cvt_tf32(v.z), cvt_tf32(v.w));
            *(uint4*)&Bs[row][c4] = u;
        }
        __syncthreads();
        // ---- 2 k8 steps of mma ----
        #pragma unroll
        for (int kb = 0; kb < 16; kb += 8) {
            unsigned af[2][4];
            #pragma unroll
            for (int mt = 0; mt < 2; mt++) {
                int r = wm + mt * 16 + gq;
                af[mt][0] = As[r][kb + qc];
                af[mt][1] = As[r + 8][kb + qc];
                af[mt][2] = As[r][kb + qc + 4];
                af[mt][3] = As[r + 8][kb + qc + 4];
            }
            #pragma unroll
            for (int nt = 0; nt < 8; nt++) {
                unsigned bf[2];
                bf[0] = Bs[kb + qc][wn + nt * 8 + gq];
                bf[1] = Bs[kb + qc + 4][wn + nt * 8 + gq];
                mma_tf32(acc[0][nt], af[0], bf);
                mma_tf32(acc[1][nt], af[1], bf);
            }
        }
        __syncthreads();
    }

    // ---- epilogue ----
    float s = 1.f, s1 = 0.f;
    if (SKIP) {
        s = 1.0f / (1.0f + expf(-skipv[0]));
        s1 = 1.0f - s;
    }
    #pragma unroll
    for (int mt = 0; mt < 2; mt++) {
        #pragma unroll
        for (int half = 0; half < 2; half++) {
            int gm = bm + wm + mt * 16 + half * 8 + gq;
            if (gm >= M) continue;
            #pragma unroll
            for (int nt = 0; nt < 8; nt++) {
                int gn = bn + wn + nt * 8 + qc * 2;
                float v0 = acc[mt][nt][half * 2 + 0];
                float v1 = acc[mt][nt][half * 2 + 1];
                if (bias) { v0 += bias[gn]; v1 += bias[gn + 1]; }
                if (SKIP) {
                    const float* hb = hres + (size_t)gm * ldc + gn;
                    v0 = s * v0 + s1 * hb[0];
                    v1 = s * v1 + s1 * hb[1];
                }
                *(float2*)(C + (size_t)gm * ldc + gn) = make_float2(v0, v1);
            }
        }
    }
}

// ---------------- edge logits + segment max (encoded atomicMax) ----------------
template <int H>
__global__ void alpha_kernel(const float* __restrict__ q, int ldq,
                             const float* __restrict__ kp, int ldk,
                             const int* __restrict__ src, const int* __restrict__ dst,
                             const float* __restrict__ p_rel,
                             float* __restrict__ alpha, unsigned int* __restrict__ amax,
                             int E, float inv_sqrt_d) {
    int e = blockIdx.x * (blockDim.x >> 5) + (threadIdx.x >> 5);
    if (e >= E) return;
    int lane = threadIdx.x & 31;
    int s = src[e], d0 = dst[e];
    const float4* qv = (const float4*)(q + (size_t)d0 * ldq);
    const float4* kv = (const float4*)(kp + (size_t)s * ldk);
    float4 q1 = qv[lane * 2], q2 = qv[lane * 2 + 1];
    float4 k1 = kv[lane * 2], k2 = kv[lane * 2 + 1];
    float part = q1.x * k1.x + q1.y * k1.y + q1.z * k1.z + q1.w * k1.w
               + q2.x * k2.x + q2.y * k2.y + q2.z * k2.z + q2.w * k2.w;
    const int G = 32 / H;   // lanes per head
    #pragma unroll
    for (int off = G / 2; off > 0; off >>= 1)
        part += __shfl_down_sync(0xffffffffu, part, off, G);
    if ((lane & (G - 1)) == 0) {
        int h = lane / G;
        float a = part * p_rel[h] * inv_sqrt_d;
        alpha[(size_t)e * H + h] = a;
        atomicMax(&amax[d0 * H + h], enc_f(a));
    }
}

// ---------------- fused exp + denom + weighted scatter-add ----------------
template <int H>
__global__ void agg_fused_kernel(const float* __restrict__ alpha,
                                 const unsigned int* __restrict__ amax,
                                 float* __restrict__ denom,
                                 const float* __restrict__ vp, int ldv,
                                 const int* __restrict__ src, const int* __restrict__ dst,
                                 float* __restrict__ agg, int E) {
    int e = blockIdx.x * (blockDim.x >> 5) + (threadIdx.x >> 5);
    if (e >= E) return;
    int lane = threadIdx.x & 31;
    int s = src[e], d0 = dst[e];
    const int G = 32 / H;
    int h = lane / G;
    float am = dec_f(amax[d0 * H + h]);
    float ex = expf(alpha[(size_t)e * H + h] - am);
    if ((lane & (G - 1)) == 0)
        atomicAdd(&denom[d0 * H + h], ex);
    const float4* vv = (const float4*)(vp + (size_t)s * ldv);
    float4 v1 = vv[lane * 2], v2 = vv[lane * 2 + 1];
    float* o = agg + (size_t)d0 * 256 + lane * 8;
    red_add_v4(o,     ex * v1.x, ex * v1.y, ex * v1.z, ex * v1.w);
    red_add_v4(o + 4, ex * v2.x, ex * v2.y, ex * v2.z, ex * v2.w);
}

// ---------------- BN stats ----------------
__global__ void bn_stats_kernel(const float* __restrict__ x, float* __restrict__ sum,
                                float* __restrict__ sumsq, int n) {
    int col = threadIdx.x;
    float s = 0.f, s2 = 0.f;
    for (int r = blockIdx.x; r < n; r += gridDim.x) {
        float v = x[(size_t)r * 256 + col];
        s += v; s2 += v * v;
    }
    atomicAdd(&sum[col], s);
    atomicAdd(&sumsq[col], s2);
}

// ---------------- BN apply + ReLU ----------------
__global__ void bn_apply_kernel(const float* __restrict__ x, float* __restrict__ y,
                                const float* __restrict__ sum, const float* __restrict__ sumsq,
                                const float* __restrict__ gamma, const float* __restrict__ beta,
                                int n) {
    int i = blockIdx.x * blockDim.x + threadIdx.x;
    if (i >= n * 256) return;
    int col = i & 255;
    float inv_n = 1.0f / (float)n;
    float mu = sum[col] * inv_n;
    float var = sumsq[col] * inv_n - mu * mu;
    float v = (x[i] - mu) * rsqrtf(var + 1e-5f) * gamma[col] + beta[col];
    y[i] = fmaxf(v, 0.f);
}

// ---------------- host orchestration ----------------
extern "C" void kernel_launch(void* const* d_in, const int* in_sizes, int n_in,
                              void* d_out, int out_size) {
    const float* x       = (const float*)d_in[0];
    const int*   ei      = (const int*)  d_in[1];
    const float* w_kqv1  = (const float*)d_in[2];
    const float* b_kqv1  = (const float*)d_in[3];
    const float* k_rel1  = (const float*)d_in[4];
    const float* v_rel1  = (const float*)d_in[5];
    const float* p_rel1  = (const float*)d_in[6];
    const float* w_out1  = (const float*)d_in[7];
    const float* b_out1  = (const float*)d_in[8];
    const float* bn_gamma = (const float*)d_in[10];
    const float* bn_beta  = (const float*)d_in[11];
    const float* w_kqv2  = (const float*)d_in[12];
    const float* b_kqv2  = (const float*)d_in[13];
    const float* k_rel2  = (const float*)d_in[14];
    const float* v_rel2  = (const float*)d_in[15];
    const float* p_rel2  = (const float*)d_in[16];
    const float* w_out2  = (const float*)d_in[17];
    const float* b_out2  = (const float*)d_in[18];
    const float* skip2   = (const float*)d_in[19];

    const int* src = ei;
    const int* dst = ei + N_EDGES;
    float* outp = (float*)d_out;

    float *kqv, *alpha, *denom, *agg, *tmp, *hbuf, *bnsum, *bnsq;
    float *w1p, *b1p, *w2p, *b2p;
    unsigned int* amax;
    cudaGetSymbolAddress((void**)&kqv,   g_kqv);
    cudaGetSymbolAddress((void**)&alpha, g_alpha);
    cudaGetSymbolAddress((void**)&amax,  g_amax);
    cudaGetSymbolAddress((void**)&denom, g_denom);
    cudaGetSymbolAddress((void**)&agg,   g_agg);
    cudaGetSymbolAddress((void**)&tmp,   g_tmp);
    cudaGetSymbolAddress((void**)&hbuf,  g_h);
    cudaGetSymbolAddress((void**)&bnsum, g_bnsum);
    cudaGetSymbolAddress((void**)&bnsq,  g_bnsq);
    cudaGetSymbolAddress((void**)&w1p,   g_w1p);
    cudaGetSymbolAddress((void**)&b1p,   g_b1p);
    cudaGetSymbolAddress((void**)&w2p,   g_w2p);
    cudaGetSymbolAddress((void**)&b2p,   g_b2p);

    const unsigned int ENC_NINF = 0x007FFFFFu;
    const int NH = N_NODES * 256;
    const int MT128 = (N_NODES + 127) / 128;   // 235

    auto zero = [&](float* p, int n) {
        fillf_kernel<<<(n + 255) / 256, 256>>>(p, 0.f, n);
    };

    // ---- weight prep (fp32, depends only on inputs) ----
    combine_kernel<<<((512 + 1) * 768 + 255) / 256, 256>>>(w_kqv1, b_kqv1, k_rel1, v_rel1,
                                                           w1p, b1p, 512, 64);
    combine_kernel<<<((256 + 1) * 768 + 255) / 256, 256>>>(w_kqv2, b_kqv2, k_rel2, v_rel2,
                                                           w2p, b2p, 256, 256);

    // ================= Layer 1 (heads=4, d=64) =================
    fillu_kernel<<<(N_NODES * 4 + 255) / 256, 256>>>(amax, ENC_NINF, N_NODES * 4);
    zero(denom, N_NODES * 4);
    zero(agg, NH);
    zero(bnsum, 256);
    zero(bnsq, 256);

    // kqv = x @ W1' + b1' : [30000,512] x [512,768] -> kp|q|vp
    gemm_tf32<0,0><<<dim3(768 / 128, MT128), 256>>>(x, w1p, b1p, kqv,
        N_NODES, 512, 768, 512, 768, 768, nullptr, 0, 0, nullptr, nullptr);
    // edge logits + segment max (kp at cols [0,256), q at [256,512))
    alpha_kernel<4><<<(N_EDGES + 7) / 8, 256>>>(kqv + 256, 768, kqv, 768, src, dst, p_rel1,
                                                alpha, amax, N_EDGES, 0.125f);
    // fused exp + denom + scatter-add (vp at cols [512,768))
    agg_fused_kernel<4><<<(N_EDGES + 7) / 8, 256>>>(alpha, amax, denom, kqv + 512, 768,
                                                    src, dst, agg, N_EDGES);
    // out1 = gelu(agg / denom) @ w_out1 + b_out1
    gemm_tf32<2,0><<<dim3(256 / 128, MT128), 256>>>(agg, w_out1, b_out1, tmp,
        N_NODES, 256, 256, 256, 256, 256, denom, 6, 4, nullptr, nullptr);
    // BN + ReLU -> hbuf
    bn_stats_kernel<<<256, 256>>>(tmp, bnsum, bnsq, N_NODES);
    bn_apply_kernel<<<(NH + 255) / 256, 256>>>(tmp, hbuf, bnsum, bnsq, bn_gamma, bn_beta, N_NODES);

    // ================= Layer 2 (heads=1, d=256) =================
    fillu_kernel<<<(N_NODES + 255) / 256, 256>>>(amax, ENC_NINF, N_NODES);
    zero(denom, N_NODES);
    zero(agg, NH);

    gemm_tf32<0,0><<<dim3(768 / 128, MT128), 256>>>(hbuf, w2p, b2p, kqv,
        N_NODES, 256, 768, 256, 768, 768, nullptr, 0, 0, nullptr, nullptr);
    alpha_kernel<1><<<(N_EDGES + 7) / 8, 256>>>(kqv + 256, 768, kqv, 768, src, dst, p_rel2,
                                                alpha, amax, N_EDGES, 0.0625f);
    agg_fused_kernel<1><<<(N_EDGES + 7) / 8, 256>>>(alpha, amax, denom, kqv + 512, 768,
                                                    src, dst, agg, N_EDGES);
    // out2 = gelu(agg / denom) @ w_out2 + b_out2, fused skip gate -> d_out
    gemm_tf32<2,1><<<dim3(256 / 128, MT128), 256>>>(agg, w_out2, b_out2, outp,
        N_NODES, 256, 256, 256, 256, 256, denom, 8, 1, skip2, hbuf);

    (void)in_sizes; (void)n_in; (void)out_size;
}

// round 6
// speedup vs baseline: 5.7987x; 1.5173x over previous
#include <cuda_runtime.h>
#include <math.h>

#define N_NODES 30000
#define N_EDGES 480000

// ---------------- scratch (static device globals; no allocation) ----------------
__device__ float g_kqv[N_NODES * 768];     // kp|q|vp packed (both layers)
__device__ float g_agg[N_NODES * 256];     // normalized attention output
__device__ float g_tmp[N_NODES * 256];     // out1 pre-BN
__device__ float g_h  [N_NODES * 256];     // post BN+ReLU (needed for skip)
__device__ float g_bnsum[256];
__device__ float g_bnsq [256];
__device__ float g_w1p[512 * 768];         // combined L1 weights
__device__ float g_b1p[768];
__device__ float g_w2p[256 * 768];         // combined L2 weights
__device__ float g_b2p[768];
__device__ int   g_count [N_NODES];        // CSR build
__device__ int   g_off   [N_NODES + 1];
__device__ int   g_cursor[N_NODES];
__device__ int   g_esrc  [N_EDGES];        // src ids sorted by dst

// ---------------- helpers ----------------
__device__ __forceinline__ float gelu_exact(float v) {
    return 0.5f * v * (1.0f + erff(v * 0.70710678118654752f));
}
__device__ __forceinline__ unsigned cvt_tf32(float f) {
    unsigned u;
    asm("cvt.rna.tf32.f32 %0, %1;" : "=r"(u) : "f"(f));
    return u;
}
__device__ __forceinline__ void mma_tf32(float* d, const unsigned* a, const unsigned* b) {
    asm volatile("mma.sync.aligned.m16n8k8.row.col.f32.tf32.tf32.f32 "
                 "{%0,%1,%2,%3}, {%4,%5,%6,%7}, {%8,%9}, {%0,%1,%2,%3};"
                 : "+f"(d[0]), "+f"(d[1]), "+f"(d[2]), "+f"(d[3])
                 : "r"(a[0]), "r"(a[1]), "r"(a[2]), "r"(a[3]), "r"(b[0]), "r"(b[1]));
}

// ---------------- weight combine: W' = [Wk@Krel_bd | Wq | Wv@Vrel_bd] ----------------
__global__ void combine_kernel(const float* __restrict__ W, const float* __restrict__ b,
                               const float* __restrict__ krel, const float* __restrict__ vrel,
                               float* __restrict__ Wp, float* __restrict__ bp,
                               int IN, int D) {
    int idx = blockIdx.x * blockDim.x + threadIdx.x;
    if (idx >= (IN + 1) * 768) return;
    int row = idx / 768, c = idx % 768;
    const float* src = (row < IN) ? (W + (size_t)row * 768) : b;
    float val;
    if (c >= 256 && c < 512) {
        val = src[c];
    } else {
        const float* rel = (c < 256) ? krel : vrel;
        int cc = (c < 256) ? c : (c - 512);
        int base = (c < 256) ? 0 : 512;
        int h = cc / D, e = cc % D;
        float s = 0.f;
        for (int d = 0; d < D; d++)
            s += src[base + h * D + d] * rel[(h * D + d) * D + e];
        val = s;
    }
    if (row < IN) Wp[(size_t)row * 768 + c] = val;
    else          bp[c] = val;
}

// ---------------- CSR build ----------------
__global__ void zero_init_kernel(int* __restrict__ count, float* __restrict__ bnsum,
                                 float* __restrict__ bnsq) {
    int i = blockIdx.x * blockDim.x + threadIdx.x;
    if (i < N_NODES) count[i] = 0;
    if (i < 256) { bnsum[i] = 0.f; bnsq[i] = 0.f; }
}
__global__ void hist_kernel(const int* __restrict__ dst, int* __restrict__ count) {
    int i = blockIdx.x * blockDim.x + threadIdx.x;
    if (i < N_EDGES) atomicAdd(&count[dst[i]], 1);
}
// single-block exclusive scan over N_NODES counts -> off, cursor
__global__ void scan_kernel(const int* __restrict__ count, int* __restrict__ off,
                            int* __restrict__ cursor) {
    __shared__ int part[1024];
    const int tid = threadIdx.x;
    const int chunk = (N_NODES + 1023) / 1024;   // 30
    const int start = tid * chunk;
    int s = 0;
    for (int i = 0; i < chunk; i++) {
        int idx = start + i;
        if (idx < N_NODES) s += count[idx];
    }
    part[tid] = s;
    __syncthreads();
    // inclusive Hillis-Steele scan
    for (int o = 1; o < 1024; o <<= 1) {
        int v = (tid >= o) ? part[tid - o] : 0;
        __syncthreads();
        part[tid] += v;
        __syncthreads();
    }
    int run = (tid > 0) ? part[tid - 1] : 0;
    for (int i = 0; i < chunk; i++) {
        int idx = start + i;
        if (idx < N_NODES) {
            off[idx] = run;
            cursor[idx] = run;
            run += count[idx];
        }
    }
    if (tid == 0) off[N_NODES] = part[1023];
}
__global__ void scatter_kernel(const int* __restrict__ src, const int* __restrict__ dst,
                               int* __restrict__ cursor, int* __restrict__ esrc) {
    int i = blockIdx.x * blockDim.x + threadIdx.x;
    if (i >= N_EDGES) return;
    int p = atomicAdd(&cursor[dst[i]], 1);
    esrc[p] = src[i];
}

// ---------------- fused attention: warp per dst, online softmax, no atomics ----------------
// q/kp/vp are column slices of kqv (ld = 768). agg row written normalized.
template <int H>
__global__ void attn_kernel(const float* __restrict__ q, const float* __restrict__ kp,
                            const float* __restrict__ vp,
                            const int* __restrict__ off, const int* __restrict__ esrc,
                            const float* __restrict__ p_rel,
                            float* __restrict__ agg, float inv_sqrt_d) {
    int w = blockIdx.x * (blockDim.x >> 5) + (threadIdx.x >> 5);
    if (w >= N_NODES) return;
    const int lane = threadIdx.x & 31;
    const int G = 32 / H;          // lanes per head group
    const int h = lane / G;
    const float pr = p_rel[h] * inv_sqrt_d;

    // load q row once: 8 floats per lane
    const float4* qv = (const float4*)(q + (size_t)w * 768);
    float4 q1 = qv[lane * 2], q2 = qv[lane * 2 + 1];

    int beg = off[w], end = off[w + 1];
    float m = -INFINITY, denom = 0.f;
    float a0 = 0.f, a1 = 0.f, a2 = 0.f, a3 = 0.f;
    float a4 = 0.f, a5 = 0.f, a6 = 0.f, a7 = 0.f;

    for (int e = beg; e < end; e++) {
        int s = esrc[e];
        const float4* kv = (const float4*)(kp + (size_t)s * 768);
        const float4* vv = (const float4*)(vp + (size_t)s * 768);
        float4 k1 = kv[lane * 2], k2 = kv[lane * 2 + 1];
        float4 v1 = vv[lane * 2], v2 = vv[lane * 2 + 1];
        float part = q1.x * k1.x + q1.y * k1.y + q1.z * k1.z + q1.w * k1.w
                   + q2.x * k2.x + q2.y * k2.y + q2.z * k2.z + q2.w * k2.w;
        #pragma unroll
        for (int o = G / 2; o > 0; o >>= 1)
            part += __shfl_xor_sync(0xffffffffu, part, o);
        float a = part * pr;             // replicated across head group
        if (a > m) {
            float c = expf(m - a);       // exp(-inf)=0 on first edge
            denom *= c;
            a0 *= c; a1 *= c; a2 *= c; a3 *= c;
            a4 *= c; a5 *= c; a6 *= c; a7 *= c;
            m = a;
        }
        float ex = expf(a - m);
        denom += ex;
        a0 += ex * v1.x; a1 += ex * v1.y; a2 += ex * v1.z; a3 += ex * v1.w;
        a4 += ex * v2.x; a5 += ex * v2.y; a6 += ex * v2.z; a7 += ex * v2.w;
    }
    float invd = 1.0f / (denom + 1e-16f);
    float4* o4 = (float4*)(agg + (size_t)w * 256);
    o4[lane * 2]     = make_float4(a0 * invd, a1 * invd, a2 * invd, a3 * invd);
    o4[lane * 2 + 1] = make_float4(a4 * invd, a5 * invd, a6 * invd, a7 * invd);
}

// ---------------- tf32 tensor-core GEMM with register prefetch ----------------
// C[M,N] = act(A)[M,K] @ B[K,N] (+bias) (+skip blend)
// ACT: 0 = identity, 1 = gelu on A elements. K%16==0, N%128==0.
template <int ACT, int SKIP>
__global__ void gemm_tf32(const float* __restrict__ A, const float* __restrict__ B,
                          const float* __restrict__ bias, float* __restrict__ C,
                          int M, int K, int N, int lda, int ldb, int ldc,
                          const float* __restrict__ skipv, const float* __restrict__ hres) {
    __shared__ unsigned As[128][20];
    __shared__ unsigned Bs[16][136];
    const int bm = blockIdx.y * 128;
    const int bn = blockIdx.x * 128;
    const int tid = threadIdx.x;        // 256
    const int wid = tid >> 5, lane = tid & 31;
    const int wm = (wid >> 1) * 32;
    const int wn = (wid & 1) * 64;
    const int gq = lane >> 2;
    const int qc = lane & 3;

    // loader addressing (loop-invariant)
    const int arow = tid >> 2;                 // 0..63
    const int akq  = (tid & 3) * 4;            // 0,4,8,12
    const int gmA0 = bm + arow, gmA1 = bm + arow + 64;
    const int brow = tid >> 5;                 // 0..7
    const int bc   = (tid & 31) * 4;

    float acc[2][8][4] = {};
    const float4 z4 = make_float4(0.f, 0.f, 0.f, 0.f);
    float4 ra0, ra1, rb0, rb1;

    // prologue: prefetch k0 = 0
    ra0 = (gmA0 < M) ? *(const float4*)(A + (size_t)gmA0 * lda + akq) : z4;
    ra1 = (gmA1 < M) ? *(const float4*)(A + (size_t)gmA1 * lda + akq) : z4;
    rb0 = *(const float4*)(B + (size_t)brow * ldb + bn + bc);
    rb1 = *(const float4*)(B + (size_t)(brow + 8) * ldb + bn + bc);

    for (int k0 = 0; k0 < K; k0 += 16) {
        // ---- store current tile to smem (ACT + cvt) ----
        float4 va0 = ra0, va1 = ra1;
        if (ACT == 1) {
            va0.x = gelu_exact(va0.x); va0.y = gelu_exact(va0.y);
            va0.z = gelu_exact(va0.z); va0.w = gelu_exact(va0.w);
            va1.x = gelu_exact(va1.x); va1.y = gelu_exact(va1.y);
            va1.z = gelu_exact(va1.z); va1.w = gelu_exact(va1.w);
        }
        *(uint4*)&As[arow][akq] =
            make_uint4(cvt_tf32(va0.x), cvt_tf32(va0.y), cvt_tf32(va0.z), cvt_tf32(va0.w));
        *(uint4*)&As[arow + 64][akq] =
            make_uint4(cvt_tf32(va1.x), cvt_tf32(va1.y), cvt_tf32(va1.z), cvt_tf32(va1.w));
        *(uint4*)&Bs[brow][bc] =
            make_uint4(cvt_tf32(rb0.x), cvt_tf32(rb0.y), cvt_tf32(rb0.z), cvt_tf32(rb0.w));
        *(uint4*)&Bs[brow + 8][bc] =
            make_uint4(cvt_tf32(rb1.x), cvt_tf32(rb1.y), cvt_tf32(rb1.z), cvt_tf32(rb1.w));
        __syncthreads();

        // ---- prefetch next tile (overlaps with mma below) ----
        int kn = k0 + 16;
        if (kn < K) {
            ra0 = (gmA0 < M) ? *(const float4*)(A + (size_t)gmA0 * lda + kn + akq) : z4;
            ra1 = (gmA1 < M) ? *(const float4*)(A + (size_t)gmA1 * lda + kn + akq) : z4;
            rb0 = *(const float4*)(B + (size_t)(kn + brow) * ldb + bn + bc);
            rb1 = *(const float4*)(B + (size_t)(kn + brow + 8) * ldb + bn + bc);
        }

        // ---- 2 k8 mma steps ----
        #pragma unroll
        for (int kb = 0; kb < 16; kb += 8) {
            unsigned af[2][4];
            #pragma unroll
            for (int mt = 0; mt < 2; mt++) {
                int r = wm + mt * 16 + gq;
                af[mt][0] = As[r][kb + qc];
                af[mt][1] = As[r + 8][kb + qc];
                af[mt][2] = As[r][kb + qc + 4];
                af[mt][3] = As[r + 8][kb + qc + 4];
            }
            #pragma unroll
            for (int nt = 0; nt < 8; nt++) {
                unsigned bf[2];
                bf[0] = Bs[kb + qc][wn + nt * 8 + gq];
                bf[1] = Bs[kb + qc + 4][wn + nt * 8 + gq];
                mma_tf32(acc[0][nt], af[0], bf);
                mma_tf32(acc[1][nt], af[1], bf);
            }
        }
        __syncthreads();
    }

    // ---- epilogue ----
    float s = 1.f, s1 = 0.f;
    if (SKIP) {
        s = 1.0f / (1.0f + expf(-skipv[0]));
        s1 = 1.0f - s;
    }
    #pragma unroll
    for (int mt = 0; mt < 2; mt++) {
        #pragma unroll
        for (int half = 0; half < 2; half++) {
            int gm = bm + wm + mt * 16 + half * 8 + gq;
            if (gm >= M) continue;
            #pragma unroll
            for (int nt = 0; nt < 8; nt++) {
                int gn = bn + wn + nt * 8 + qc * 2;
                float v0 = acc[mt][nt][half * 2 + 0];
                float v1 = acc[mt][nt][half * 2 + 1];
                if (bias) { v0 += bias[gn]; v1 += bias[gn + 1]; }
                if (SKIP) {
                    const float* hb = hres + (size_t)gm * ldc + gn;
                    v0 = s * v0 + s1 * hb[0];
                    v1 = s * v1 + s1 * hb[1];
                }
                *(float2*)(C + (size_t)gm * ldc + gn) = make_float2(v0, v1);
            }
        }
    }
}

// ---------------- BN stats ----------------
__global__ void bn_stats_kernel(const float* __restrict__ x, float* __restrict__ sum,
                                float* __restrict__ sumsq, int n) {
    int col = threadIdx.x;
    float s = 0.f, s2 = 0.f;
    for (int r = blockIdx.x; r < n; r += gridDim.x) {
        float v = x[(size_t)r * 256 + col];
        s += v; s2 += v * v;
    }
    atomicAdd(&sum[col], s);
    atomicAdd(&sumsq[col], s2);
}

// ---------------- BN apply + ReLU ----------------
__global__ void bn_apply_kernel(const float* __restrict__ x, float* __restrict__ y,
                                const float* __restrict__ sum, const float* __restrict__ sumsq,
                                const float* __restrict__ gamma, const float* __restrict__ beta,
                                int n) {
    int i = blockIdx.x * blockDim.x + threadIdx.x;
    if (i >= n * 256) return;
    int col = i & 255;
    float inv_n = 1.0f / (float)n;
    float mu = sum[col] * inv_n;
    float var = sumsq[col] * inv_n - mu * mu;
    float v = (x[i] - mu) * rsqrtf(var + 1e-5f) * gamma[col] + beta[col];
    y[i] = fmaxf(v, 0.f);
}

// ---------------- host orchestration ----------------
extern "C" void kernel_launch(void* const* d_in, const int* in_sizes, int n_in,
                              void* d_out, int out_size) {
    const float* x       = (const float*)d_in[0];
    const int*   ei      = (const int*)  d_in[1];
    const float* w_kqv1  = (const float*)d_in[2];
    const float* b_kqv1  = (const float*)d_in[3];
    const float* k_rel1  = (const float*)d_in[4];
    const float* v_rel1  = (const float*)d_in[5];
    const float* p_rel1  = (const float*)d_in[6];
    const float* w_out1  = (const float*)d_in[7];
    const float* b_out1  = (const float*)d_in[8];
    const float* bn_gamma = (const float*)d_in[10];
    const float* bn_beta  = (const float*)d_in[11];
    const float* w_kqv2  = (const float*)d_in[12];
    const float* b_kqv2  = (const float*)d_in[13];
    const float* k_rel2  = (const float*)d_in[14];
    const float* v_rel2  = (const float*)d_in[15];
    const float* p_rel2  = (const float*)d_in[16];
    const float* w_out2  = (const float*)d_in[17];
    const float* b_out2  = (const float*)d_in[18];
    const float* skip2   = (const float*)d_in[19];

    const int* src = ei;
    const int* dst = ei + N_EDGES;
    float* outp = (float*)d_out;

    float *kqv, *agg, *tmp, *hbuf, *bnsum, *bnsq;
    float *w1p, *b1p, *w2p, *b2p;
    int *count, *off, *cursor, *esrc;
    cudaGetSymbolAddress((void**)&kqv,    g_kqv);
    cudaGetSymbolAddress((void**)&agg,    g_agg);
    cudaGetSymbolAddress((void**)&tmp,    g_tmp);
    cudaGetSymbolAddress((void**)&hbuf,   g_h);
    cudaGetSymbolAddress((void**)&bnsum,  g_bnsum);
    cudaGetSymbolAddress((void**)&bnsq,   g_bnsq);
    cudaGetSymbolAddress((void**)&w1p,    g_w1p);
    cudaGetSymbolAddress((void**)&b1p,    g_b1p);
    cudaGetSymbolAddress((void**)&w2p,    g_w2p);
    cudaGetSymbolAddress((void**)&b2p,    g_b2p);
    cudaGetSymbolAddress((void**)&count,  g_count);
    cudaGetSymbolAddress((void**)&off,    g_off);
    cudaGetSymbolAddress((void**)&cursor, g_cursor);
    cudaGetSymbolAddress((void**)&esrc,   g_esrc);

    const int NH = N_NODES * 256;
    const int MT128 = (N_NODES + 127) / 128;   // 235
    const int ATTN_BLOCKS = (N_NODES + 7) / 8; // 8 warps per 256-thread block

    // ---- weight prep ----
    combine_kernel<<<((512 + 1) * 768 + 255) / 256, 256>>>(w_kqv1, b_kqv1, k_rel1, v_rel1,
                                                           w1p, b1p, 512, 64);
    combine_kernel<<<((256 + 1) * 768 + 255) / 256, 256>>>(w_kqv2, b_kqv2, k_rel2, v_rel2,
                                                           w2p, b2p, 256, 256);

    // ---- CSR build (per call; deterministic given inputs) ----
    zero_init_kernel<<<(N_NODES + 255) / 256, 256>>>(count, bnsum, bnsq);
    hist_kernel<<<(N_EDGES + 255) / 256, 256>>>(dst, count);
    scan_kernel<<<1, 1024>>>(count, off, cursor);
    scatter_kernel<<<(N_EDGES + 255) / 256, 256>>>(src, dst, cursor, esrc);

    // ================= Layer 1 (heads=4, d=64) =================
    gemm_tf32<0,0><<<dim3(768 / 128, MT128), 256>>>(x, w1p, b1p, kqv,
        N_NODES, 512, 768, 512, 768, 768, nullptr, nullptr);
    attn_kernel<4><<<ATTN_BLOCKS, 256>>>(kqv + 256, kqv, kqv + 512, off, esrc, p_rel1,
                                         agg, 0.125f);
    gemm_tf32<1,0><<<dim3(256 / 128, MT128), 256>>>(agg, w_out1, b_out1, tmp,
        N_NODES, 256, 256, 256, 256, 256, nullptr, nullptr);
    bn_stats_kernel<<<256, 256>>>(tmp, bnsum, bnsq, N_NODES);
    bn_apply_kernel<<<(NH + 255) / 256, 256>>>(tmp, hbuf, bnsum, bnsq, bn_gamma, bn_beta, N_NODES);

    // ================= Layer 2 (heads=1, d=256) =================
    gemm_tf32<0,0><<<dim3(768 / 128, MT128), 256>>>(hbuf, w2p, b2p, kqv,
        N_NODES, 256, 768, 256, 768, 768, nullptr, nullptr);
    attn_kernel<1><<<ATTN_BLOCKS, 256>>>(kqv + 256, kqv, kqv + 512, off, esrc, p_rel2,
                                         agg, 0.0625f);
    gemm_tf32<1,1><<<dim3(256 / 128, MT128), 256>>>(agg, w_out2, b_out2, outp,
        N_NODES, 256, 256, 256, 256, 256, skip2, hbuf);

    (void)in_sizes; (void)n_in; (void)out_size;
}

// round 8
// speedup vs baseline: 6.3189x; 1.0897x over previous
#include <cuda_runtime.h>
#include <math.h>

#define N_NODES 30000
#define N_EDGES 480000

// ---------------- scratch (static device globals; no allocation) ----------------
__device__ float g_kqv[N_NODES * 768];     // kp|q|vp packed (both layers)
__device__ float g_agg[N_NODES * 256];     // normalized attention output
__device__ float g_tmp[N_NODES * 256];     // out1 pre-BN
__device__ float g_h  [N_NODES * 256];     // post BN+ReLU (needed for skip)
__device__ float g_bnsum[256];
__device__ float g_bnsq [256];
__device__ float g_w1p[512 * 768];         // combined L1 weights
__device__ float g_b1p[768];
__device__ float g_w2p[256 * 768];         // combined L2 weights
__device__ float g_b2p[768];
__device__ int   g_count [N_NODES];        // CSR build
__device__ int   g_off   [N_NODES + 1];
__device__ int   g_cursor[N_NODES];
__device__ int   g_esrc  [N_EDGES];        // src ids sorted by dst

// ---------------- helpers ----------------
__device__ __forceinline__ float gelu_exact(float v) {
    return 0.5f * v * (1.0f + erff(v * 0.70710678118654752f));
}
__device__ __forceinline__ unsigned cvt_tf32(float f) {
    unsigned u;
    asm("cvt.rna.tf32.f32 %0, %1;" : "=r"(u) : "f"(f));
    return u;
}
__device__ __forceinline__ void mma_tf32(float* d, const unsigned* a, const unsigned* b) {
    asm volatile("mma.sync.aligned.m16n8k8.row.col.f32.tf32.tf32.f32 "
                 "{%0,%1,%2,%3}, {%4,%5,%6,%7}, {%8,%9}, {%0,%1,%2,%3};"
                 : "+f"(d[0]), "+f"(d[1]), "+f"(d[2]), "+f"(d[3])
                 : "r"(a[0]), "r"(a[1]), "r"(a[2]), "r"(a[3]), "r"(b[0]), "r"(b[1]));
}

// ---------------- weight combine: W' = [Wk@Krel_bd | Wq | Wv@Vrel_bd] ----------------
__global__ void combine_kernel(const float* __restrict__ W, const float* __restrict__ b,
                               const float* __restrict__ krel, const float* __restrict__ vrel,
                               float* __restrict__ Wp, float* __restrict__ bp,
                               int IN, int D) {
    int idx = blockIdx.x * blockDim.x + threadIdx.x;
    if (idx >= (IN + 1) * 768) return;
    int row = idx / 768, c = idx % 768;
    const float* src = (row < IN) ? (W + (size_t)row * 768) : b;
    float val;
    if (c >= 256 && c < 512) {
        val = src[c];
    } else {
        const float* rel = (c < 256) ? krel : vrel;
        int cc = (c < 256) ? c : (c - 512);
        int base = (c < 256) ? 0 : 512;
        int h = cc / D, e = cc % D;
        float s = 0.f;
        for (int d = 0; d < D; d++)
            s += src[base + h * D + d] * rel[(h * D + d) * D + e];
        val = s;
    }
    if (row < IN) Wp[(size_t)row * 768 + c] = val;
    else          bp[c] = val;
}

// ---------------- CSR build ----------------
__global__ void zero_init_kernel(int* __restrict__ count, float* __restrict__ bnsum,
                                 float* __restrict__ bnsq) {
    int i = blockIdx.x * blockDim.x + threadIdx.x;
    if (i < N_NODES) count[i] = 0;
    if (i < 256) { bnsum[i] = 0.f; bnsq[i] = 0.f; }
}
__global__ void hist_kernel(const int* __restrict__ dst, int* __restrict__ count) {
    int i = blockIdx.x * blockDim.x + threadIdx.x;
    if (i < N_EDGES) atomicAdd(&count[dst[i]], 1);
}
__global__ void scan_kernel(const int* __restrict__ count, int* __restrict__ off,
                            int* __restrict__ cursor) {
    __shared__ int part[1024];
    const int tid = threadIdx.x;
    const int chunk = (N_NODES + 1023) / 1024;
    const int start = tid * chunk;
    int s = 0;
    for (int i = 0; i < chunk; i++) {
        int idx = start + i;
        if (idx < N_NODES) s += count[idx];
    }
    part[tid] = s;
    __syncthreads();
    for (int o = 1; o < 1024; o <<= 1) {
        int v = (tid >= o) ? part[tid - o] : 0;
        __syncthreads();
        part[tid] += v;
        __syncthreads();
    }
    int run = (tid > 0) ? part[tid - 1] : 0;
    for (int i = 0; i < chunk; i++) {
        int idx = start + i;
        if (idx < N_NODES) {
            off[idx] = run;
            cursor[idx] = run;
            run += count[idx];
        }
    }
    if (tid == 0) off[N_NODES] = part[1023];
}
__global__ void scatter_kernel(const int* __restrict__ src, const int* __restrict__ dst,
                               int* __restrict__ cursor, int* __restrict__ esrc) {
    int i = blockIdx.x * blockDim.x + threadIdx.x;
    if (i >= N_EDGES) return;
    int p = atomicAdd(&cursor[dst[i]], 1);
    esrc[p] = src[i];
}

// ---------------- fused attention: warp per dst, 2-edge online softmax ----------------
template <int H>
__global__ void attn_kernel(const float* __restrict__ q, const float* __restrict__ kp,
                            const float* __restrict__ vp,
                            const int* __restrict__ off, const int* __restrict__ esrc,
                            const float* __restrict__ p_rel,
                            float* __restrict__ agg, float inv_sqrt_d) {
    int w = blockIdx.x * (blockDim.x >> 5) + (threadIdx.x >> 5);
    if (w >= N_NODES) return;
    const int lane = threadIdx.x & 31;
    const int G = 32 / H;
    const int h = lane / G;
    const float pr = p_rel[h] * inv_sqrt_d;

    const float4* qv = (const float4*)(q + (size_t)w * 768);
    float4 q1 = qv[lane * 2], q2 = qv[lane * 2 + 1];

    int beg = off[w], end = off[w + 1];
    float m = -INFINITY, denom = 0.f;
    float a0 = 0.f, a1 = 0.f, a2 = 0.f, a3 = 0.f;
    float a4 = 0.f, a5 = 0.f, a6 = 0.f, a7 = 0.f;

    int e = beg;
    for (; e + 1 < end; e += 2) {
        int s0 = esrc[e], s1 = esrc[e + 1];
        const float4* kv0 = (const float4*)(kp + (size_t)s0 * 768);
        const float4* kv1 = (const float4*)(kp + (size_t)s1 * 768);
        const float4* vv0 = (const float4*)(vp + (size_t)s0 * 768);
        const float4* vv1 = (const float4*)(vp + (size_t)s1 * 768);
        float4 k01 = kv0[lane * 2], k02 = kv0[lane * 2 + 1];
        float4 k11 = kv1[lane * 2], k12 = kv1[lane * 2 + 1];
        float4 v01 = vv0[lane * 2], v02 = vv0[lane * 2 + 1];
        float4 v11 = vv1[lane * 2], v12 = vv1[lane * 2 + 1];
        float d0 = q1.x * k01.x + q1.y * k01.y + q1.z * k01.z + q1.w * k01.w
                 + q2.x * k02.x + q2.y * k02.y + q2.z * k02.z + q2.w * k02.w;
        float d1 = q1.x * k11.x + q1.y * k11.y + q1.z * k11.z + q1.w * k11.w
                 + q2.x * k12.x + q2.y * k12.y + q2.z * k12.z + q2.w * k12.w;
        #pragma unroll
        for (int o = G / 2; o > 0; o >>= 1) {
            d0 += __shfl_xor_sync(0xffffffffu, d0, o);
            d1 += __shfl_xor_sync(0xffffffffu, d1, o);
        }
        float l0 = d0 * pr, l1 = d1 * pr;
        float mm = fmaxf(m, fmaxf(l0, l1));
        float c  = expf(m - mm);          // ==1 when unchanged; 0 on first pair
        float e0 = expf(l0 - mm);
        float e1 = expf(l1 - mm);
        m = mm;
        denom = denom * c + e0 + e1;
        a0 = a0 * c + e0 * v01.x + e1 * v11.x;
        a1 = a1 * c + e0 * v01.y + e1 * v11.y;
        a2 = a2 * c + e0 * v01.z + e1 * v11.z;
        a3 = a3 * c + e0 * v01.w + e1 * v11.w;
        a4 = a4 * c + e0 * v02.x + e1 * v12.x;
        a5 = a5 * c + e0 * v02.y + e1 * v12.y;
        a6 = a6 * c + e0 * v02.z + e1 * v12.z;
        a7 = a7 * c + e0 * v02.w + e1 * v12.w;
    }
    if (e < end) {      // tail edge
        int s0 = esrc[e];
        const float4* kv0 = (const float4*)(kp + (size_t)s0 * 768);
        const float4* vv0 = (const float4*)(vp + (size_t)s0 * 768);
        float4 k01 = kv0[lane * 2], k02 = kv0[lane * 2 + 1];
        float4 v01 = vv0[lane * 2], v02 = vv0[lane * 2 + 1];
        float d0 = q1.x * k01.x + q1.y * k01.y + q1.z * k01.z + q1.w * k01.w
                 + q2.x * k02.x + q2.y * k02.y + q2.z * k02.z + q2.w * k02.w;
        #pragma unroll
        for (int o = G / 2; o > 0; o >>= 1)
            d0 += __shfl_xor_sync(0xffffffffu, d0, o);
        float l0 = d0 * pr;
        float mm = fmaxf(m, l0);
        float c  = expf(m - mm);
        float e0 = expf(l0 - mm);
        m = mm;
        denom = denom * c + e0;
        a0 = a0 * c + e0 * v01.x; a1 = a1 * c + e0 * v01.y;
        a2 = a2 * c + e0 * v01.z; a3 = a3 * c + e0 * v01.w;
        a4 = a4 * c + e0 * v02.x; a5 = a5 * c + e0 * v02.y;
        a6 = a6 * c + e0 * v02.z; a7 = a7 * c + e0 * v02.w;
    }
    float invd = 1.0f / (denom + 1e-16f);
    float4* o4 = (float4*)(agg + (size_t)w * 256);
    o4[lane * 2]     = make_float4(a0 * invd, a1 * invd, a2 * invd, a3 * invd);
    o4[lane * 2 + 1] = make_float4(a4 * invd, a5 * invd, a6 * invd, a7 * invd);
}

// ---------------- tf32 GEMM: 128x128x32 tiles, double-buffered dynamic smem ----------------
// C[M,N] = act(A)[M,K] @ B[K,N] (+bias) (+skip blend)
// ACT: 0 = identity, 1 = gelu on A elements. K%32==0, N%128==0.
#define AS(b,r,c) sA[(b)*128*36 + (r)*36 + (c)]
#define BS(b,r,c) sB[(b)*32*136 + (r)*136 + (c)]
#define GEMM_SMEM ((2*128*36 + 2*32*136) * 4)

template <int ACT, int SKIP>
__global__ __launch_bounds__(256)
void gemm_tf32(const float* __restrict__ A, const float* __restrict__ B,
               const float* __restrict__ bias, float* __restrict__ C,
               int M, int K, int N, int lda, int ldb, int ldc,
               const float* __restrict__ skipv, const float* __restrict__ hres) {
    extern __shared__ unsigned char smem_raw[];
    unsigned* sA = (unsigned*)smem_raw;                       // [2][128][36]
    unsigned* sB = (unsigned*)(smem_raw + 2 * 128 * 36 * 4);  // [2][32][136]

    const int bm = blockIdx.y * 128;
    const int bn = blockIdx.x * 128;
    const int tid = threadIdx.x;        // 256
    const int wid = tid >> 5, lane = tid & 31;
    const int wm = (wid >> 1) * 32;
    const int wn = (wid & 1) * 64;
    const int gq = lane >> 2;
    const int qc = lane & 3;

    // loader addressing: A: 1024 float4 per stage -> 4/thread; same for B
    const int arow = tid >> 3;            // 0..31 (+32*l)
    const int akq  = (tid & 7) * 4;       // 0..28
    const int brow = tid >> 5;            // 0..7 (+8*l)
    const int bc   = (tid & 31) * 4;

    float acc[2][8][4] = {};
    const float4 z4 = make_float4(0.f, 0.f, 0.f, 0.f);

    // ---- prologue: load stage 0 directly ----
    #pragma unroll
    for (int l = 0; l < 4; l++) {
        int row = arow + l * 32;
        int gm = bm + row;
        float4 v = (gm < M) ? *(const float4*)(A + (size_t)gm * lda + akq) : z4;
        if (ACT == 1) {
            v.x = gelu_exact(v.x); v.y = gelu_exact(v.y);
            v.z = gelu_exact(v.z); v.w = gelu_exact(v.w);
        }
        *(uint4*)&AS(0, row, akq) =
            make_uint4(cvt_tf32(v.x), cvt_tf32(v.y), cvt_tf32(v.z), cvt_tf32(v.w));
        int rb = brow + l * 8;
        float4 b4 = *(const float4*)(B + (size_t)rb * ldb + bn + bc);
        *(uint4*)&BS(0, rb, bc) =
            make_uint4(cvt_tf32(b4.x), cvt_tf32(b4.y), cvt_tf32(b4.z), cvt_tf32(b4.w));
    }
    __syncthreads();

    for (int k0 = 0; k0 < K; k0 += 32) {
        const int cur = (k0 >> 5) & 1, nxt = cur ^ 1;
        const int kn = k0 + 32;
        const bool have_next = kn < K;

        // ---- issue next-stage LDGs (latency hidden under mma below) ----
        float4 ra[4], rb4[4];
        if (have_next) {
            #pragma unroll
            for (int l = 0; l < 4; l++) {
                int gm = bm + arow + l * 32;
                ra[l] = (gm < M) ? *(const float4*)(A + (size_t)gm * lda + kn + akq) : z4;
                rb4[l] = *(const float4*)(B + (size_t)(kn + brow + l * 8) * ldb + bn + bc);
            }
        }

        // ---- 4 k8 mma steps on current buffer ----
        #pragma unroll
        for (int kb = 0; kb < 32; kb += 8) {
            unsigned af[2][4];
            #pragma unroll
            for (int mt = 0; mt < 2; mt++) {
                int r = wm + mt * 16 + gq;
                af[mt][0] = AS(cur, r,     kb + qc);
                af[mt][1] = AS(cur, r + 8, kb + qc);
                af[mt][2] = AS(cur, r,     kb + qc + 4);
                af[mt][3] = AS(cur, r + 8, kb + qc + 4);
            }
            #pragma unroll
            for (int nt = 0; nt < 8; nt++) {
                unsigned bf[2];
                bf[0] = BS(cur, kb + qc,     wn + nt * 8 + gq);
                bf[1] = BS(cur, kb + qc + 4, wn + nt * 8 + gq);
                mma_tf32(acc[0][nt], af[0], bf);
                mma_tf32(acc[1][nt], af[1], bf);
            }
        }

        // ---- store next stage ----
        if (have_next) {
            #pragma unroll
            for (int l = 0; l < 4; l++) {
                float4 v = ra[l];
                if (ACT == 1) {
                    v.x = gelu_exact(v.x); v.y = gelu_exact(v.y);
                    v.z = gelu_exact(v.z); v.w = gelu_exact(v.w);
                }
                *(uint4*)&AS(nxt, arow + l * 32, akq) =
                    make_uint4(cvt_tf32(v.x), cvt_tf32(v.y), cvt_tf32(v.z), cvt_tf32(v.w));
                float4 b4 = rb4[l];
                *(uint4*)&BS(nxt, brow + l * 8, bc) =
                    make_uint4(cvt_tf32(b4.x), cvt_tf32(b4.y), cvt_tf32(b4.z), cvt_tf32(b4.w));
            }
        }
        __syncthreads();
    }

    // ---- epilogue ----
    float s = 1.f, s1 = 0.f;
    if (SKIP) {
        s = 1.0f / (1.0f + expf(-skipv[0]));
        s1 = 1.0f - s;
    }
    #pragma unroll
    for (int mt = 0; mt < 2; mt++) {
        #pragma unroll
        for (int half = 0; half < 2; half++) {
            int gm = bm + wm + mt * 16 + half * 8 + gq;
            if (gm >= M) continue;
            #pragma unroll
            for (int nt = 0; nt < 8; nt++) {
                int gn = bn + wn + nt * 8 + qc * 2;
                float v0 = acc[mt][nt][half * 2 + 0];
                float v1 = acc[mt][nt][half * 2 + 1];
                if (bias) { v0 += bias[gn]; v1 += bias[gn + 1]; }
                if (SKIP) {
                    const float* hb = hres + (size_t)gm * ldc + gn;
                    v0 = s * v0 + s1 * hb[0];
                    v1 = s * v1 + s1 * hb[1];
                }
                *(float2*)(C + (size_t)gm * ldc + gn) = make_float2(v0, v1);
            }
        }
    }
}

// ---------------- BN stats ----------------
__global__ void bn_stats_kernel(const float* __restrict__ x, float* __restrict__ sum,
                                float* __restrict__ sumsq, int n) {
    int col = threadIdx.x;
    float s = 0.f, s2 = 0.f;
    for (int r = blockIdx.x; r < n; r += gridDim.x) {
        float v = x[(size_t)r * 256 + col];
        s += v; s2 += v * v;
    }
    atomicAdd(&sum[col], s);
    atomicAdd(&sumsq[col], s2);
}

// ---------------- BN apply + ReLU ----------------
__global__ void bn_apply_kernel(const float* __restrict__ x, float* __restrict__ y,
                                const float* __restrict__ sum, const float* __restrict__ sumsq,
                                const float* __restrict__ gamma, const float* __restrict__ beta,
                                int n) {
    int i = blockIdx.x * blockDim.x + threadIdx.x;
    if (i >= n * 256) return;
    int col = i & 255;
    float inv_n = 1.0f / (float)n;
    float mu = sum[col] * inv_n;
    float var = sumsq[col] * inv_n - mu * mu;
    float v = (x[i] - mu) * rsqrtf(var + 1e-5f) * gamma[col] + beta[col];
    y[i] = fmaxf(v, 0.f);
}

// ---------------- host orchestration ----------------
extern "C" void kernel_launch(void* const* d_in, const int* in_sizes, int n_in,
                              void* d_out, int out_size) {
    const float* x       = (const float*)d_in[0];
    const int*   ei      = (const int*)  d_in[1];
    const float* w_kqv1  = (const float*)d_in[2];
    const float* b_kqv1  = (const float*)d_in[3];
    const float* k_rel1  = (const float*)d_in[4];
    const float* v_rel1  = (const float*)d_in[5];
    const float* p_rel1  = (const float*)d_in[6];
    const float* w_out1  = (const float*)d_in[7];
    const float* b_out1  = (const float*)d_in[8];
    const float* bn_gamma = (const float*)d_in[10];
    const float* bn_beta  = (const float*)d_in[11];
    const float* w_kqv2  = (const float*)d_in[12];
    const float* b_kqv2  = (const float*)d_in[13];
    const float* k_rel2  = (const float*)d_in[14];
    const float* v_rel2  = (const float*)d_in[15];
    const float* p_rel2  = (const float*)d_in[16];
    const float* w_out2  = (const float*)d_in[17];
    const float* b_out2  = (const float*)d_in[18];
    const float* skip2   = (const float*)d_in[19];

    const int* src = ei;
    const int* dst = ei + N_EDGES;
    float* outp = (float*)d_out;

    float *kqv, *agg, *tmp, *hbuf, *bnsum, *bnsq;
    float *w1p, *b1p, *w2p, *b2p;
    int *count, *off, *cursor, *esrc;
    cudaGetSymbolAddress((void**)&kqv,    g_kqv);
    cudaGetSymbolAddress((void**)&agg,    g_agg);
    cudaGetSymbolAddress((void**)&tmp,    g_tmp);
    cudaGetSymbolAddress((void**)&hbuf,   g_h);
    cudaGetSymbolAddress((void**)&bnsum,  g_bnsum);
    cudaGetSymbolAddress((void**)&bnsq,   g_bnsq);
    cudaGetSymbolAddress((void**)&w1p,    g_w1p);
    cudaGetSymbolAddress((void**)&b1p,    g_b1p);
    cudaGetSymbolAddress((void**)&w2p,    g_w2p);
    cudaGetSymbolAddress((void**)&b2p,    g_b2p);
    cudaGetSymbolAddress((void**)&count,  g_count);
    cudaGetSymbolAddress((void**)&off,    g_off);
    cudaGetSymbolAddress((void**)&cursor, g_cursor);
    cudaGetSymbolAddress((void**)&esrc,   g_esrc);

    // allow >48KB dynamic smem for the GEMM instantiations (idempotent)
    cudaFuncSetAttribute(gemm_tf32<0,0>, cudaFuncAttributeMaxDynamicSharedMemorySize, GEMM_SMEM);
    cudaFuncSetAttribute(gemm_tf32<1,0>, cudaFuncAttributeMaxDynamicSharedMemorySize, GEMM_SMEM);
    cudaFuncSetAttribute(gemm_tf32<1,1>, cudaFuncAttributeMaxDynamicSharedMemorySize, GEMM_SMEM);

    const int NH = N_NODES * 256;
    const int MT128 = (N_NODES + 127) / 128;   // 235
    const int ATTN_BLOCKS = (N_NODES + 7) / 8;

    // ---- weight prep ----
    combine_kernel<<<((512 + 1) * 768 + 255) / 256, 256>>>(w_kqv1, b_kqv1, k_rel1, v_rel1,
                                                           w1p, b1p, 512, 64);
    combine_kernel<<<((256 + 1) * 768 + 255) / 256, 256>>>(w_kqv2, b_kqv2, k_rel2, v_rel2,
                                                           w2p, b2p, 256, 256);

    // ---- CSR build ----
    zero_init_kernel<<<(N_NODES + 255) / 256, 256>>>(count, bnsum, bnsq);
    hist_kernel<<<(N_EDGES + 255) / 256, 256>>>(dst, count);
    scan_kernel<<<1, 1024>>>(count, off, cursor);
    scatter_kernel<<<(N_EDGES + 255) / 256, 256>>>(src, dst, cursor, esrc);

    // ================= Layer 1 (heads=4, d=64) =================
    gemm_tf32<0,0><<<dim3(768 / 128, MT128), 256, GEMM_SMEM>>>(x, w1p, b1p, kqv,
        N_NODES, 512, 768, 512, 768, 768, nullptr, nullptr);
    attn_kernel<4><<<ATTN_BLOCKS, 256>>>(kqv + 256, kqv, kqv + 512, off, esrc, p_rel1,
                                         agg, 0.125f);
    gemm_tf32<1,0><<<dim3(256 / 128, MT128), 256, GEMM_SMEM>>>(agg, w_out1, b_out1, tmp,
        N_NODES, 256, 256, 256, 256, 256, nullptr, nullptr);
    bn_stats_kernel<<<256, 256>>>(tmp, bnsum, bnsq, N_NODES);
    bn_apply_kernel<<<(NH + 255) / 256, 256>>>(tmp, hbuf, bnsum, bnsq, bn_gamma, bn_beta, N_NODES);

    // ================= Layer 2 (heads=1, d=256) =================
    gemm_tf32<0,0><<<dim3(768 / 128, MT128), 256, GEMM_SMEM>>>(hbuf, w2p, b2p, kqv,
        N_NODES, 256, 768, 256, 768, 768, nullptr, nullptr);
    attn_kernel<1><<<ATTN_BLOCKS, 256>>>(kqv + 256, kqv, kqv + 512, off, esrc, p_rel2,
                                         agg, 0.0625f);
    gemm_tf32<1,1><<<dim3(256 / 128, MT128), 256, GEMM_SMEM>>>(agg, w_out2, b_out2, outp,
        N_NODES, 256, 256, 256, 256, 256, skip2, hbuf);

    (void)in_sizes; (void)n_in; (void)out_size;
}

// round 10
// speedup vs baseline: 6.7524x; 1.0686x over previous
#include <cuda_runtime.h>
#include <cuda_fp16.h>
#include <math.h>

#define N_NODES 30000
#define N_EDGES 480000

// ---------------- scratch (static device globals; no allocation) ----------------
__device__ float g_kqv[N_NODES * 768];     // kp|q|vp packed fp32 (q cols used by attn)
__device__ __half g_kph[N_NODES * 256];    // fp16 kp for edge gather
__device__ __half g_vph[N_NODES * 256];    // fp16 vp for edge gather
__device__ float g_agg[N_NODES * 256];     // normalized attention output
__device__ float g_tmp[N_NODES * 256];     // out1 pre-BN
__device__ float g_bnsum[256];
__device__ float g_bnsq [256];
__device__ float g_w1p[512 * 768];         // combined L1 weights
__device__ float g_b1p[768];
__device__ float g_w2p[256 * 768];         // combined L2 weights
__device__ float g_b2p[768];
__device__ int   g_count [N_NODES];        // CSR build
__device__ int   g_off   [N_NODES + 1];
__device__ int   g_cursor[N_NODES];
__device__ int   g_esrc  [N_EDGES];        // src ids sorted by dst

// ---------------- helpers ----------------
__device__ __forceinline__ float gelu_exact(float v) {
    return 0.5f * v * (1.0f + erff(v * 0.70710678118654752f));
}
__device__ __forceinline__ float bn_relu(float v, int col,
                                         const float* __restrict__ bnsum,
                                         const float* __restrict__ bnsq,
                                         const float* __restrict__ gamma,
                                         const float* __restrict__ beta) {
    const float inv_n = 1.0f / (float)N_NODES;
    float mu = bnsum[col] * inv_n;
    float var = bnsq[col] * inv_n - mu * mu;
    float r = (v - mu) * rsqrtf(var + 1e-5f) * gamma[col] + beta[col];
    return fmaxf(r, 0.f);
}
__device__ __forceinline__ unsigned cvt_tf32(float f) {
    unsigned u;
    asm("cvt.rna.tf32.f32 %0, %1;" : "=r"(u) : "f"(f));
    return u;
}
__device__ __forceinline__ void mma_tf32(float* d, const unsigned* a, const unsigned* b) {
    asm volatile("mma.sync.aligned.m16n8k8.row.col.f32.tf32.tf32.f32 "
                 "{%0,%1,%2,%3}, {%4,%5,%6,%7}, {%8,%9}, {%0,%1,%2,%3};"
                 : "+f"(d[0]), "+f"(d[1]), "+f"(d[2]), "+f"(d[3])
                 : "r"(a[0]), "r"(a[1]), "r"(a[2]), "r"(a[3]), "r"(b[0]), "r"(b[1]));
}
__device__ __forceinline__ float dot8h(float4 q1, float4 q2, uint4 ku) {
    const __half2* kh = (const __half2*)&ku;
    float2 a = __half22float2(kh[0]);
    float2 b = __half22float2(kh[1]);
    float2 c = __half22float2(kh[2]);
    float2 d = __half22float2(kh[3]);
    return q1.x * a.x + q1.y * a.y + q1.z * b.x + q1.w * b.y
         + q2.x * c.x + q2.y * c.y + q2.z * d.x + q2.w * d.y;
}

// ---------------- weight combine: W' = [Wk@Krel_bd | Wq | Wv@Vrel_bd] ----------------
__global__ void combine_kernel(const float* __restrict__ W, const float* __restrict__ b,
                               const float* __restrict__ krel, const float* __restrict__ vrel,
                               float* __restrict__ Wp, float* __restrict__ bp,
                               int IN, int D) {
    int idx = blockIdx.x * blockDim.x + threadIdx.x;
    if (idx >= (IN + 1) * 768) return;
    int row = idx / 768, c = idx % 768;
    const float* src = (row < IN) ? (W + (size_t)row * 768) : b;
    float val;
    if (c >= 256 && c < 512) {
        val = src[c];
    } else {
        const float* rel = (c < 256) ? krel : vrel;
        int cc = (c < 256) ? c : (c - 512);
        int base = (c < 256) ? 0 : 512;
        int h = cc / D, e = cc % D;
        float s = 0.f;
        for (int d = 0; d < D; d++)
            s += src[base + h * D + d] * rel[(h * D + d) * D + e];
        val = s;
    }
    if (row < IN) Wp[(size_t)row * 768 + c] = val;
    else          bp[c] = val;
}

// ---------------- CSR build ----------------
__global__ void zero_init_kernel(int* __restrict__ count, float* __restrict__ bnsum,
                                 float* __restrict__ bnsq) {
    int i = blockIdx.x * blockDim.x + threadIdx.x;
    if (i < N_NODES) count[i] = 0;
    if (i < 256) { bnsum[i] = 0.f; bnsq[i] = 0.f; }
}
__global__ void hist_kernel(const int* __restrict__ dst, int* __restrict__ count) {
    int i = blockIdx.x * blockDim.x + threadIdx.x;
    if (i < N_EDGES) atomicAdd(&count[dst[i]], 1);
}
__global__ void scan_kernel(const int* __restrict__ count, int* __restrict__ off,
                            int* __restrict__ cursor) {
    __shared__ int part[1024];
    const int tid = threadIdx.x;
    const int chunk = (N_NODES + 1023) / 1024;
    const int start = tid * chunk;
    int s = 0;
    for (int i = 0; i < chunk; i++) {
        int idx = start + i;
        if (idx < N_NODES) s += count[idx];
    }
    part[tid] = s;
    __syncthreads();
    for (int o = 1; o < 1024; o <<= 1) {
        int v = (tid >= o) ? part[tid - o] : 0;
        __syncthreads();
        part[tid] += v;
        __syncthreads();
    }
    int run = (tid > 0) ? part[tid - 1] : 0;
    for (int i = 0; i < chunk; i++) {
        int idx = start + i;
        if (idx < N_NODES) {
            off[idx] = run;
            cursor[idx] = run;
            run += count[idx];
        }
    }
    if (tid == 0) off[N_NODES] = part[1023];
}
__global__ void scatter_kernel(const int* __restrict__ src, const int* __restrict__ dst,
                               int* __restrict__ cursor, int* __restrict__ esrc) {
    int i = blockIdx.x * blockDim.x + threadIdx.x;
    if (i >= N_EDGES) return;
    int p = atomicAdd(&cursor[dst[i]], 1);
    esrc[p] = src[i];
}

// ---------------- fused attention: warp per dst, 2-edge online softmax, fp16 k/v ----------------
template <int H>
__global__ void attn_kernel(const float* __restrict__ q,
                            const __half* __restrict__ kph, const __half* __restrict__ vph,
                            const int* __restrict__ off, const int* __restrict__ esrc,
                            const float* __restrict__ p_rel,
                            float* __restrict__ agg, float inv_sqrt_d) {
    int w = blockIdx.x * (blockDim.x >> 5) + (threadIdx.x >> 5);
    if (w >= N_NODES) return;
    const int lane = threadIdx.x & 31;
    const int G = 32 / H;
    const int h = lane / G;
    const float pr = p_rel[h] * inv_sqrt_d;

    const float4* qv = (const float4*)(q + (size_t)w * 768);
    float4 q1 = qv[lane * 2], q2 = qv[lane * 2 + 1];

    int beg = off[w], end = off[w + 1];
    float m = -INFINITY, denom = 0.f;
    float a0 = 0.f, a1 = 0.f, a2 = 0.f, a3 = 0.f;
    float a4 = 0.f, a5 = 0.f, a6 = 0.f, a7 = 0.f;

    int e = beg;
    for (; e + 1 < end; e += 2) {
        int s0 = esrc[e], s1 = esrc[e + 1];
        uint4 ku0 = ((const uint4*)(kph + (size_t)s0 * 256))[lane];
        uint4 ku1 = ((const uint4*)(kph + (size_t)s1 * 256))[lane];
        uint4 vu0 = ((const uint4*)(vph + (size_t)s0 * 256))[lane];
        uint4 vu1 = ((const uint4*)(vph + (size_t)s1 * 256))[lane];
        float d0 = dot8h(q1, q2, ku0);
        float d1 = dot8h(q1, q2, ku1);
        #pragma unroll
        for (int o = G / 2; o > 0; o >>= 1) {
            d0 += __shfl_xor_sync(0xffffffffu, d0, o);
            d1 += __shfl_xor_sync(0xffffffffu, d1, o);
        }
        float l0 = d0 * pr, l1 = d1 * pr;
        float mm = fmaxf(m, fmaxf(l0, l1));
        float c  = expf(m - mm);
        float e0 = expf(l0 - mm);
        float e1 = expf(l1 - mm);
        m = mm;
        denom = denom * c + e0 + e1;
        const __half2* v0h = (const __half2*)&vu0;
        const __half2* v1h = (const __half2*)&vu1;
        float2 p0 = __half22float2(v0h[0]), p1 = __half22float2(v0h[1]);
        float2 p2 = __half22float2(v0h[2]), p3 = __half22float2(v0h[3]);
        float2 r0 = __half22float2(v1h[0]), r1 = __half22float2(v1h[1]);
        float2 r2 = __half22float2(v1h[2]), r3 = __half22float2(v1h[3]);
        a0 = a0 * c + e0 * p0.x + e1 * r0.x;
        a1 = a1 * c + e0 * p0.y + e1 * r0.y;
        a2 = a2 * c + e0 * p1.x + e1 * r1.x;
        a3 = a3 * c + e0 * p1.y + e1 * r1.y;
        a4 = a4 * c + e0 * p2.x + e1 * r2.x;
        a5 = a5 * c + e0 * p2.y + e1 * r2.y;
        a6 = a6 * c + e0 * p3.x + e1 * r3.x;
        a7 = a7 * c + e0 * p3.y + e1 * r3.y;
    }
    if (e < end) {      // tail edge
        int s0 = esrc[e];
        uint4 ku0 = ((const uint4*)(kph + (size_t)s0 * 256))[lane];
        uint4 vu0 = ((const uint4*)(vph + (size_t)s0 * 256))[lane];
        float d0 = dot8h(q1, q2, ku0);
        #pragma unroll
        for (int o = G / 2; o > 0; o >>= 1)
            d0 += __shfl_xor_sync(0xffffffffu, d0, o);
        float l0 = d0 * pr;
        float mm = fmaxf(m, l0);
        float c  = expf(m - mm);
        float e0 = expf(l0 - mm);
        m = mm;
        denom = denom * c + e0;
        const __half2* v0h = (const __half2*)&vu0;
        float2 p0 = __half22float2(v0h[0]), p1 = __half22float2(v0h[1]);
        float2 p2 = __half22float2(v0h[2]), p3 = __half22float2(v0h[3]);
        a0 = a0 * c + e0 * p0.x; a1 = a1 * c + e0 * p0.y;
        a2 = a2 * c + e0 * p1.x; a3 = a3 * c + e0 * p1.y;
        a4 = a4 * c + e0 * p2.x; a5 = a5 * c + e0 * p2.y;
        a6 = a6 * c + e0 * p3.x; a7 = a7 * c + e0 * p3.y;
    }
    float invd = 1.0f / (denom + 1e-16f);
    float4* o4 = (float4*)(agg + (size_t)w * 256);
    o4[lane * 2]     = make_float4(a0 * invd, a1 * invd, a2 * invd, a3 * invd);
    o4[lane * 2 + 1] = make_float4(a4 * invd, a5 * invd, a6 * invd, a7 * invd);
}

// ---------------- tf32 GEMM: 128x128x32 tiles, double-buffered dynamic smem ----------------
// ACT: 0 = identity, 1 = gelu(A), 3 = BN+ReLU(A) via stats (A cols are BN features)
// SKIP: 0 = none, 2 = blend with relu(bn(hres)) recomputed in epilogue
// PACKH: 1 = write fp16 k (cols<256) / v (cols>=512) to kph/vph; fp32 store only q cols
#define AS(b,r,c) sA[(b)*128*36 + (r)*36 + (c)]
#define BS(b,r,c) sB[(b)*32*136 + (r)*136 + (c)]
#define GEMM_SMEM ((2*128*36 + 2*32*136) * 4)

template <int ACT, int SKIP, int PACKH>
__global__ __launch_bounds__(256)
void gemm_tf32(const float* __restrict__ A, const float* __restrict__ B,
               const float* __restrict__ bias, float* __restrict__ C,
               int M, int K, int N, int lda, int ldb, int ldc,
               const float* __restrict__ skipv, const float* __restrict__ hres,
               const float* __restrict__ bnsum, const float* __restrict__ bnsq,
               const float* __restrict__ gamma, const float* __restrict__ beta,
               __half* __restrict__ kph, __half* __restrict__ vph) {
    extern __shared__ unsigned char smem_raw[];
    unsigned* sA = (unsigned*)smem_raw;                       // [2][128][36]
    unsigned* sB = (unsigned*)(smem_raw + 2 * 128 * 36 * 4);  // [2][32][136]

    const int bm = blockIdx.y * 128;
    const int bn = blockIdx.x * 128;
    const int tid = threadIdx.x;        // 256
    const int wid = tid >> 5, lane = tid & 31;
    const int wm = (wid >> 1) * 32;
    const int wn = (wid & 1) * 64;
    const int gq = lane >> 2;
    const int qc = lane & 3;

    const int arow = tid >> 3;            // 0..31 (+32*l)
    const int akq  = (tid & 7) * 4;       // 0..28
    const int brow = tid >> 5;            // 0..7 (+8*l)
    const int bc   = (tid & 31) * 4;

    float acc[2][8][4] = {};
    const float4 z4 = make_float4(0.f, 0.f, 0.f, 0.f);

    // ---- prologue: load stage 0 ----
    #pragma unroll
    for (int l = 0; l < 4; l++) {
        int row = arow + l * 32;
        int gm = bm + row;
        float4 v = (gm < M) ? *(const float4*)(A + (size_t)gm * lda + akq) : z4;
        if (ACT == 1) {
            v.x = gelu_exact(v.x); v.y = gelu_exact(v.y);
            v.z = gelu_exact(v.z); v.w = gelu_exact(v.w);
        } else if (ACT == 3) {
            v.x = bn_relu(v.x, akq + 0, bnsum, bnsq, gamma, beta);
            v.y = bn_relu(v.y, akq + 1, bnsum, bnsq, gamma, beta);
            v.z = bn_relu(v.z, akq + 2, bnsum, bnsq, gamma, beta);
            v.w = bn_relu(v.w, akq + 3, bnsum, bnsq, gamma, beta);
        }
        *(uint4*)&AS(0, row, akq) =
            make_uint4(cvt_tf32(v.x), cvt_tf32(v.y), cvt_tf32(v.z), cvt_tf32(v.w));
        int rb = brow + l * 8;
        float4 b4 = *(const float4*)(B + (size_t)rb * ldb + bn + bc);
        *(uint4*)&BS(0, rb, bc) =
            make_uint4(cvt_tf32(b4.x), cvt_tf32(b4.y), cvt_tf32(b4.z), cvt_tf32(b4.w));
    }
    __syncthreads();

    for (int k0 = 0; k0 < K; k0 += 32) {
        const int cur = (k0 >> 5) & 1, nxt = cur ^ 1;
        const int kn = k0 + 32;
        const bool have_next = kn < K;

        float4 ra[4], rb4[4];
        if (have_next) {
            #pragma unroll
            for (int l = 0; l < 4; l++) {
                int gm = bm + arow + l * 32;
                ra[l] = (gm < M) ? *(const float4*)(A + (size_t)gm * lda + kn + akq) : z4;
                rb4[l] = *(const float4*)(B + (size_t)(kn + brow + l * 8) * ldb + bn + bc);
            }
        }

        #pragma unroll
        for (int kb = 0; kb < 32; kb += 8) {
            unsigned af[2][4];
            #pragma unroll
            for (int mt = 0; mt < 2; mt++) {
                int r = wm + mt * 16 + gq;
                af[mt][0] = AS(cur, r,     kb + qc);
                af[mt][1] = AS(cur, r + 8, kb + qc);
                af[mt][2] = AS(cur, r,     kb + qc + 4);
                af[mt][3] = AS(cur, r + 8, kb + qc + 4);
            }
            #pragma unroll
            for (int nt = 0; nt < 8; nt++) {
                unsigned bf[2];
                bf[0] = BS(cur, kb + qc,     wn + nt * 8 + gq);
                bf[1] = BS(cur, kb + qc + 4, wn + nt * 8 + gq);
                mma_tf32(acc[0][nt], af[0], bf);
                mma_tf32(acc[1][nt], af[1], bf);
            }
        }

        if (have_next) {
            #pragma unroll
            for (int l = 0; l < 4; l++) {
                float4 v = ra[l];
                if (ACT == 1) {
                    v.x = gelu_exact(v.x); v.y = gelu_exact(v.y);
                    v.z = gelu_exact(v.z); v.w = gelu_exact(v.w);
                } else if (ACT == 3) {
                    v.x = bn_relu(v.x, kn + akq + 0, bnsum, bnsq, gamma, beta);
                    v.y = bn_relu(v.y, kn + akq + 1, bnsum, bnsq, gamma, beta);
                    v.z = bn_relu(v.z, kn + akq + 2, bnsum, bnsq, gamma, beta);
                    v.w = bn_relu(v.w, kn + akq + 3, bnsum, bnsq, gamma, beta);
                }
                *(uint4*)&AS(nxt, arow + l * 32, akq) =
                    make_uint4(cvt_tf32(v.x), cvt_tf32(v.y), cvt_tf32(v.z), cvt_tf32(v.w));
                float4 b4 = rb4[l];
                *(uint4*)&BS(nxt, brow + l * 8, bc) =
                    make_uint4(cvt_tf32(b4.x), cvt_tf32(b4.y), cvt_tf32(b4.z), cvt_tf32(b4.w));
            }
        }
        __syncthreads();
    }

    // ---- epilogue ----
    float s = 1.f, s1 = 0.f;
    if (SKIP == 2) {
        s = 1.0f / (1.0f + expf(-skipv[0]));
        s1 = 1.0f - s;
    }
    #pragma unroll
    for (int mt = 0; mt < 2; mt++) {
        #pragma unroll
        for (int half = 0; half < 2; half++) {
            int gm = bm + wm + mt * 16 + half * 8 + gq;
            if (gm >= M) continue;
            #pragma unroll
            for (int nt = 0; nt < 8; nt++) {
                int gn = bn + wn + nt * 8 + qc * 2;
                float v0 = acc[mt][nt][half * 2 + 0];
                float v1 = acc[mt][nt][half * 2 + 1];
                if (bias) { v0 += bias[gn]; v1 += bias[gn + 1]; }
                if (SKIP == 2) {
                    const float* hb = hres + (size_t)gm * ldc + gn;
                    float h0 = bn_relu(hb[0], gn,     bnsum, bnsq, gamma, beta);
                    float h1 = bn_relu(hb[1], gn + 1, bnsum, bnsq, gamma, beta);
                    v0 = s * v0 + s1 * h0;
                    v1 = s * v1 + s1 * h1;
                }
                if (PACKH) {
                    if (gn < 256) {
                        *(__half2*)(kph + (size_t)gm * 256 + gn) = __floats2half2_rn(v0, v1);
                    } else if (gn >= 512) {
                        *(__half2*)(vph + (size_t)gm * 256 + gn - 512) = __floats2half2_rn(v0, v1);
                    } else {
                        *(float2*)(C + (size_t)gm * ldc + gn) = make_float2(v0, v1);
                    }
                } else {
                    *(float2*)(C + (size_t)gm * ldc + gn) = make_float2(v0, v1);
                }
            }
        }
    }
}

// ---------------- BN stats ----------------
__global__ void bn_stats_kernel(const float* __restrict__ x, float* __restrict__ sum,
                                float* __restrict__ sumsq, int n) {
    int col = threadIdx.x;
    float s = 0.f, s2 = 0.f;
    for (int r = blockIdx.x; r < n; r += gridDim.x) {
        float v = x[(size_t)r * 256 + col];
        s += v; s2 += v * v;
    }
    atomicAdd(&sum[col], s);
    atomicAdd(&sumsq[col], s2);
}

// ---------------- host orchestration ----------------
extern "C" void kernel_launch(void* const* d_in, const int* in_sizes, int n_in,
                              void* d_out, int out_size) {
    const float* x       = (const float*)d_in[0];
    const int*   ei      = (const int*)  d_in[1];
    const float* w_kqv1  = (const float*)d_in[2];
    const float* b_kqv1  = (const float*)d_in[3];
    const float* k_rel1  = (const float*)d_in[4];
    const float* v_rel1  = (const float*)d_in[5];
    const float* p_rel1  = (const float*)d_in[6];
    const float* w_out1  = (const float*)d_in[7];
    const float* b_out1  = (const float*)d_in[8];
    const float* bn_gamma = (const float*)d_in[10];
    const float* bn_beta  = (const float*)d_in[11];
    const float* w_kqv2  = (const float*)d_in[12];
    const float* b_kqv2  = (const float*)d_in[13];
    const float* k_rel2  = (const float*)d_in[14];
    const float* v_rel2  = (const float*)d_in[15];
    const float* p_rel2  = (const float*)d_in[16];
    const float* w_out2  = (const float*)d_in[17];
    const float* b_out2  = (const float*)d_in[18];
    const float* skip2   = (const float*)d_in[19];

    const int* src = ei;
    const int* dst = ei + N_EDGES;
    float* outp = (float*)d_out;

    float *kqv, *agg, *tmp, *bnsum, *bnsq;
    float *w1p, *b1p, *w2p, *b2p;
    __half *kph, *vph;
    int *count, *off, *cursor, *esrc;
    cudaGetSymbolAddress((void**)&kqv,    g_kqv);
    cudaGetSymbolAddress((void**)&kph,    g_kph);
    cudaGetSymbolAddress((void**)&vph,    g_vph);
    cudaGetSymbolAddress((void**)&agg,    g_agg);
    cudaGetSymbolAddress((void**)&tmp,    g_tmp);
    cudaGetSymbolAddress((void**)&bnsum,  g_bnsum);
    cudaGetSymbolAddress((void**)&bnsq,   g_bnsq);
    cudaGetSymbolAddress((void**)&w1p,    g_w1p);
    cudaGetSymbolAddress((void**)&b1p,    g_b1p);
    cudaGetSymbolAddress((void**)&w2p,    g_w2p);
    cudaGetSymbolAddress((void**)&b2p,    g_b2p);
    cudaGetSymbolAddress((void**)&count,  g_count);
    cudaGetSymbolAddress((void**)&off,    g_off);
    cudaGetSymbolAddress((void**)&cursor, g_cursor);
    cudaGetSymbolAddress((void**)&esrc,   g_esrc);

    cudaFuncSetAttribute(gemm_tf32<0,0,1>, cudaFuncAttributeMaxDynamicSharedMemorySize, GEMM_SMEM);
    cudaFuncSetAttribute(gemm_tf32<3,0,1>, cudaFuncAttributeMaxDynamicSharedMemorySize, GEMM_SMEM);
    cudaFuncSetAttribute(gemm_tf32<1,0,0>, cudaFuncAttributeMaxDynamicSharedMemorySize, GEMM_SMEM);
    cudaFuncSetAttribute(gemm_tf32<1,2,0>, cudaFuncAttributeMaxDynamicSharedMemorySize, GEMM_SMEM);

    const int MT128 = (N_NODES + 127) / 128;   // 235
    const int ATTN_BLOCKS = (N_NODES + 7) / 8;

    // ---- weight prep ----
    combine_kernel<<<((512 + 1) * 768 + 255) / 256, 256>>>(w_kqv1, b_kqv1, k_rel1, v_rel1,
                                                           w1p, b1p, 512, 64);
    combine_kernel<<<((256 + 1) * 768 + 255) / 256, 256>>>(w_kqv2, b_kqv2, k_rel2, v_rel2,
                                                           w2p, b2p, 256, 256);

    // ---- CSR build ----
    zero_init_kernel<<<(N_NODES + 255) / 256, 256>>>(count, bnsum, bnsq);
    hist_kernel<<<(N_EDGES + 255) / 256, 256>>>(dst, count);
    scan_kernel<<<1, 1024>>>(count, off, cursor);
    scatter_kernel<<<(N_EDGES + 255) / 256, 256>>>(src, dst, cursor, esrc);

    // ================= Layer 1 (heads=4, d=64) =================
    // kqv = x @ W1' + b1' : q cols fp32 to kqv; k/v cols packed fp16 to kph/vph
    gemm_tf32<0,0,1><<<dim3(768 / 128, MT128), 256, GEMM_SMEM>>>(x, w1p, b1p, kqv,
        N_NODES, 512, 768, 512, 768, 768, nullptr, nullptr,
        nullptr, nullptr, nullptr, nullptr, kph, vph);
    attn_kernel<4><<<ATTN_BLOCKS, 256>>>(kqv + 256, kph, vph, off, esrc, p_rel1,
                                         agg, 0.125f);
    gemm_tf32<1,0,0><<<dim3(256 / 128, MT128), 256, GEMM_SMEM>>>(agg, w_out1, b_out1, tmp,
        N_NODES, 256, 256, 256, 256, 256, nullptr, nullptr,
        nullptr, nullptr, nullptr, nullptr, nullptr, nullptr);
    bn_stats_kernel<<<256, 256>>>(tmp, bnsum, bnsq, N_NODES);

    // ================= Layer 2 (heads=1, d=256) =================
    // kqv2 GEMM applies BN+ReLU to tmp on the fly (A-load fusion)
    gemm_tf32<3,0,1><<<dim3(768 / 128, MT128), 256, GEMM_SMEM>>>(tmp, w2p, b2p, kqv,
        N_NODES, 256, 768, 256, 768, 768, nullptr, nullptr,
        bnsum, bnsq, bn_gamma, bn_beta, kph, vph);
    attn_kernel<1><<<ATTN_BLOCKS, 256>>>(kqv + 256, kph, vph, off, esrc, p_rel2,
                                         agg, 0.0625f);
    // out2 = gelu(agg) @ w_out2 + b_out2, skip blends with relu(bn(tmp)) recomputed inline
    gemm_tf32<1,2,0><<<dim3(256 / 128, MT128), 256, GEMM_SMEM>>>(agg, w_out2, b_out2, outp,
        N_NODES, 256, 256, 256, 256, 256, skip2, tmp,
        bnsum, bnsq, bn_gamma, bn_beta, nullptr, nullptr);

    (void)in_sizes; (void)n_in; (void)out_size;
}